// round 11
// baseline (speedup 1.0000x reference)
#include <cuda_runtime.h>
#include <cuda_bf16.h>
#include <math.h>
#include <stdint.h>

#define Bn 512
#define Tn 200
#define PARTY 2
#define D_M 1024
#define D_G 512
#define D_P 512
#define D_E 512

// Output layout (flattened tuple): g_, q_, e_, c_, alpha_out
#define G_OFF 0
#define Q_OFF (Bn * D_G)
#define E_OFF (Q_OFF + Bn * PARTY * D_P)
#define C_OFF (E_OFF + Bn * PARTY * D_E)
#define A_OFF (C_OFF + Bn * D_G)

// ---------------- fp32 scratch ----------------
__device__ float d_gi_buf[(Bn * PARTY) * 3 * D_G];    // gi_g (512 rows used)
__device__ float d_gie_buf[(Bn * PARTY) * 3 * D_E];   // gi_e (dedicated, avoids race)
__device__ float d_gh_buf[Bn * 3 * D_G];              // gh_g
__device__ float d_ghe_buf[(Bn * PARTY) * 3 * D_E];   // gh_e
__device__ float d_ghp_buf[(Bn * PARTY) * 3 * D_P];   // gh_p
__device__ float d_xt_buf[Bn * PARTY * D_P];
__device__ float d_gih_buf[Bn * 3 * D_P];             // gi_p dedup

// ---------------- bf16 split scratch (hi/lo concat, K tripled) ----------------
#define OFF_WIHG  0ull                       // 1536 x 4608
#define OFF_WHHG  (OFF_WIHG  + 7077888ull)   // 1536 x 1536
#define OFF_WIHP  (OFF_WHHG  + 2359296ull)   // 1536 x 4608
#define OFF_WHHP  (OFF_WIHP  + 7077888ull)   // 1536 x 1536
#define OFF_WIHE  (OFF_WHHP  + 2359296ull)   // 1536 x 1536
#define OFF_WHHE  (OFF_WIHE  + 2359296ull)   // 1536 x 1536
#define OFF_WTR   (OFF_WHHE  + 2359296ull)   // 512 x 1536
#define OFF_XCG   (OFF_WTR   + 786432ull)    // 512 x 4608 (gather-conv from U/qmask/q0)
#define OFF_GLAST (OFF_XCG   + 2359296ull)   // 512 x 1536
#define OFF_Q0    (OFF_GLAST + 786432ull)    // 1024 x 1536
#define OFF_E0SW  (OFF_Q0    + 1572864ull)   // 1024 x 1536 (gather-conv from e0)
#define OFF_E0    (OFF_E0SW  + 1572864ull)   // 1024 x 1536
#define OFF_XCP   (OFF_E0    + 1572864ull)   // 512 x 4608 (U-cols by conv; c_-cols by attn_g)
#define OFF_QC    (OFF_XCP   + 2359296ull)   // 1024 x 1536 (by attn_q)
#define BF_TOTAL  (OFF_QC    + 1572864ull)
__device__ __align__(16) __nv_bfloat16 d_bf[BF_TOTAL];

// =====================================================================
// helpers
// =====================================================================
__device__ __forceinline__ uint32_t smem_u32(const void* p) {
    uint32_t r;
    asm("{ .reg .u64 t; cvta.to.shared.u64 t, %1; cvt.u32.u64 %0, t; }" : "=r"(r) : "l"(p));
    return r;
}
__device__ __forceinline__ void cp_async16(uint32_t dst, const void* src) {
    asm volatile("cp.async.cg.shared.global [%0], [%1], 16;" :: "r"(dst), "l"(src) : "memory");
}
__device__ __forceinline__ void cp_commit() {
    asm volatile("cp.async.commit_group;" ::: "memory");
}
template<int N>
__device__ __forceinline__ void cp_wait() {
    asm volatile("cp.async.wait_group %0;" :: "n"(N) : "memory");
}
__device__ __forceinline__ void ldmatrix_x4(uint32_t& r0, uint32_t& r1, uint32_t& r2, uint32_t& r3,
                                            uint32_t addr) {
    asm volatile("ldmatrix.sync.aligned.m8n8.x4.shared.b16 {%0,%1,%2,%3}, [%4];"
                 : "=r"(r0), "=r"(r1), "=r"(r2), "=r"(r3) : "r"(addr));
}
__device__ __forceinline__ void mma_bf16(float* d, const uint32_t* a, const uint32_t* b) {
    asm volatile("mma.sync.aligned.m16n8k16.row.col.f32.bf16.bf16.f32 "
                 "{%0,%1,%2,%3}, {%4,%5,%6,%7}, {%8,%9}, {%0,%1,%2,%3};"
                 : "+f"(d[0]), "+f"(d[1]), "+f"(d[2]), "+f"(d[3])
                 : "r"(a[0]), "r"(a[1]), "r"(a[2]), "r"(a[3]), "r"(b[0]), "r"(b[1]));
}
__device__ __forceinline__ void lds128(float* v, uint32_t addr) {
    asm volatile("ld.shared.v4.f32 {%0,%1,%2,%3}, [%4];"
                 : "=f"(v[0]), "=f"(v[1]), "=f"(v[2]), "=f"(v[3]) : "r"(addr));
}
__device__ __forceinline__ void split3(float x, __nv_bfloat16* o, int stride) {
    __nv_bfloat16 hi = __float2bfloat16(x);
    __nv_bfloat16 lo = __float2bfloat16(x - __bfloat162float(hi));
    o[0] = hi; o[stride] = lo; o[2 * stride] = hi;
}
// proportional interleave: spread ng gemm blocks uniformly over total
__device__ __forceinline__ bool work_map(int bid, int ng, int total, int& widx) {
    long long p0 = ((long long)bid * ng) / total;
    long long p1 = ((long long)(bid + 1) * ng) / total;
    if (p1 > p0) { widx = (int)p0; return true; }
    widx = bid - (int)p0; return false;
}

// =====================================================================
// Attention body: per-warp online softmax, 3-deep cp.async staging.
// Smem: [tile0|tile1|tile2 16KB each][AttnSmem]
// =====================================================================
struct AttnSmem {
    float m[8]; float s[8]; float w8[8];
    float Mg, Sg;
    float sc[Tn];
    float acc[8][512];
};
#define ATTN_TILE_BYTES 16384
#define ATTN_SM_OFF (3 * ATTN_TILE_BYTES)

template<int MODE>
__device__ __forceinline__ void attn_body(
    char* smem_raw,
    const float* __restrict__ hist, size_t tstride, size_t row_off,
    const float* __restrict__ wvec,
    float* __restrict__ c_out,
    float* __restrict__ alpha_out,
    __nv_bfloat16* __restrict__ bf_out,
    int bf_stride)
{
    uint32_t sb = smem_u32(smem_raw);
    AttnSmem* sm = reinterpret_cast<AttnSmem*>(smem_raw + ATTN_SM_OFF);
    int tid = threadIdx.x;
    int lane = tid & 31;
    int w = tid >> 5;

    const float* src = hist + row_off;

    int trow_[4], c16_[4];
    #pragma unroll
    for (int i = 0; i < 4; i++) {
        int u = tid + 256 * i;
        trow_[i] = u >> 7;
        c16_[i] = u & 127;
    }

    float q[16];
    #pragma unroll
    for (int j = 0; j < 4; j++) {
        float4 t4 = *(const float4*)(wvec + lane * 4 + j * 128);
        q[j*4+0] = t4.x; q[j*4+1] = t4.y; q[j*4+2] = t4.z; q[j*4+3] = t4.w;
    }

    float m = -INFINITY, s = 0.0f;
    float acc[16];
    #pragma unroll
    for (int k = 0; k < 16; k++) acc[k] = 0.0f;

    // prologue: chunks 0..2
    #pragma unroll
    for (int c = 0; c < 3; c++) {
        uint32_t dst = sb + (uint32_t)c * ATTN_TILE_BYTES;
        #pragma unroll
        for (int i = 0; i < 4; i++) {
            cp_async16(dst + (uint32_t)(trow_[i] * 2048 + c16_[i] * 16),
                       src + (size_t)(c * 8 + trow_[i]) * tstride + c16_[i] * 4);
        }
        cp_commit();
    }

    int buf = 0;
    for (int i = 0; i < 25; i++) {
        if (i < 23) cp_wait<2>(); else if (i == 23) cp_wait<1>(); else cp_wait<0>();
        __syncthreads();

        uint32_t vbase = sb + (uint32_t)buf * ATTN_TILE_BYTES + (uint32_t)(w * 2048 + lane * 16);
        float v[16];
        #pragma unroll
        for (int j = 0; j < 4; j++) lds128(v + j * 4, vbase + j * 512);

        int t = i * 8 + w;
        float dot = 0.0f;
        #pragma unroll
        for (int k = 0; k < 16; k++) dot = fmaf(v[k], q[k], dot);
        #pragma unroll
        for (int o = 16; o > 0; o >>= 1) dot += __shfl_xor_sync(0xffffffffu, dot, o);

        if (MODE == 1 && lane == 0) sm->sc[t] = dot;

        float nm = fmaxf(m, dot);
        float rs = __expf(m - nm);
        float cf = __expf(dot - nm);
        #pragma unroll
        for (int k = 0; k < 16; k++) acc[k] = fmaf(acc[k], rs, cf * v[k]);
        s = fmaf(s, rs, cf);
        m = nm;

        __syncthreads();
        if (i + 3 < 25) {
            uint32_t dst = sb + (uint32_t)buf * ATTN_TILE_BYTES;
            #pragma unroll
            for (int j = 0; j < 4; j++) {
                cp_async16(dst + (uint32_t)(trow_[j] * 2048 + c16_[j] * 16),
                           src + (size_t)((i + 3) * 8 + trow_[j]) * tstride + c16_[j] * 4);
            }
            cp_commit();
        }
        buf = (buf == 2) ? 0 : buf + 1;
    }

    if (lane == 0) { sm->m[w] = m; sm->s[w] = s; }
    #pragma unroll
    for (int j = 0; j < 4; j++)
        #pragma unroll
        for (int u = 0; u < 4; u++)
            sm->acc[w][lane * 4 + j * 128 + u] = acc[j*4+u];
    __syncthreads();

    if (tid == 0) {
        float M = -INFINITY;
        #pragma unroll
        for (int k = 0; k < 8; k++) M = fmaxf(M, sm->m[k]);
        float S = 0.0f;
        #pragma unroll
        for (int k = 0; k < 8; k++) S += sm->s[k] * __expf(sm->m[k] - M);
        float invS = 1.0f / S;
        #pragma unroll
        for (int k = 0; k < 8; k++) sm->w8[k] = __expf(sm->m[k] - M) * invS;
        sm->Mg = M; sm->Sg = S;
    }
    __syncthreads();

    int c = tid * 2;
    float o0 = 0.0f, o1 = 0.0f;
    #pragma unroll
    for (int k = 0; k < 8; k++) {
        float wk = sm->w8[k];
        o0 = fmaf(sm->acc[k][c], wk, o0);
        o1 = fmaf(sm->acc[k][c + 1], wk, o1);
    }
    if (MODE == 1) {
        *(float2*)(c_out + c) = make_float2(o0, o1);
        split3(o0, bf_out + c,     bf_stride);
        split3(o1, bf_out + c + 1, bf_stride);
        if (tid < Tn) {
            float inv = 1.0f / sm->Sg;
            alpha_out[tid] = __expf(sm->sc[tid] - sm->Mg) * inv;
        }
    } else {
        split3(o0, bf_out + c,     bf_stride);
        split3(o1, bf_out + c + 1, bf_stride);
    }
}

// =====================================================================
// bf16 mma.sync GEMM body (R7-proven)
// =====================================================================
#define MAXT 5
struct TDesc {
    const __nv_bfloat16* A; const __nv_bfloat16* W;
    const float* bias; float* C;
    int K3; int M; int gridX; int start;
};
struct TBatch { TDesc d[MAXT]; int nd; };

#define DYN_SMEM_BYTES 66560

__device__ __forceinline__ void mma_gemm_body(const TBatch& tb, char* smem_raw, int bid)
{
    int tid = threadIdx.x;
    int wid = tid >> 5;
    int lane = tid & 31;

    int di = 0;
    #pragma unroll
    for (int k = 1; k < MAXT; k++)
        if (k < tb.nd && bid >= tb.d[k].start) di = k;
    const TDesc dd = tb.d[di];
    int local = bid - dd.start;
    int m0 = (local % dd.gridX) * 128;
    int n0 = (local / dd.gridX) * 128;
    const int K3 = dd.K3;
    const int nc = K3 >> 6;

    uint32_t sb = smem_u32(smem_raw);

    int lrow[4], lc16[4]; uint32_t swoff[4];
    #pragma unroll
    for (int i = 0; i < 4; i++) {
        int u = tid + 256 * i;
        int r = u >> 3, c16 = u & 7;
        lrow[i] = r; lc16[i] = c16;
        swoff[i] = (uint32_t)(r * 128 + 16 * (c16 ^ (r & 7)));
    }
    const __nv_bfloat16* Ab = dd.A + (size_t)n0 * K3;
    const __nv_bfloat16* Wb = dd.W + (size_t)m0 * K3;

    int xr = lane & 7;
    int lA_row = (lane & 7) + ((lane >> 3) & 1) * 8;
    int lA_kh = lane >> 4;
    int lB_row = (lane & 7) + (lane >> 4) * 8;
    int lB_kh = (lane >> 3) & 1;
    int wr = wid & 1;
    int wc = wid >> 1;
    uint32_t rbA[4], rbB[2];
    #pragma unroll
    for (int mt = 0; mt < 4; mt++) rbA[mt] = (uint32_t)((wr * 64 + mt * 16 + lA_row) * 128);
    #pragma unroll
    for (int p = 0; p < 2; p++) rbB[p] = (uint32_t)((wc * 32 + p * 16 + lB_row) * 128);

    float acc[4][4][4];
    #pragma unroll
    for (int mt = 0; mt < 4; mt++)
        #pragma unroll
        for (int nt = 0; nt < 4; nt++)
            #pragma unroll
            for (int r = 0; r < 4; r++) acc[mt][nt][r] = 0.0f;

    {
        uint32_t ba = sb, bb = sb + 16384u;
        #pragma unroll
        for (int i = 0; i < 4; i++) {
            cp_async16(ba + swoff[i], Ab + (size_t)lrow[i] * K3 + lc16[i] * 8);
            cp_async16(bb + swoff[i], Wb + (size_t)lrow[i] * K3 + lc16[i] * 8);
        }
        cp_commit();
    }

    for (int c = 0; c < nc; c++) {
        if (c + 1 < nc) {
            uint32_t ba = sb + (uint32_t)((c + 1) & 1) * 32768u;
            uint32_t bb = ba + 16384u;
            int koff = (c + 1) * 64;
            #pragma unroll
            for (int i = 0; i < 4; i++) {
                cp_async16(ba + swoff[i], Ab + (size_t)lrow[i] * K3 + koff + lc16[i] * 8);
                cp_async16(bb + swoff[i], Wb + (size_t)lrow[i] * K3 + koff + lc16[i] * 8);
            }
            cp_commit();
            cp_wait<1>();
        } else {
            cp_wait<0>();
        }
        __syncthreads();

        uint32_t ba = sb + (uint32_t)(c & 1) * 32768u;
        uint32_t bb = ba + 16384u;
        #pragma unroll
        for (int s = 0; s < 4; s++) {
            uint32_t a[4][4];
            #pragma unroll
            for (int mt = 0; mt < 4; mt++) {
                uint32_t addr = ba + rbA[mt] + 16u * (uint32_t)(((s << 1) + lA_kh) ^ xr);
                ldmatrix_x4(a[mt][0], a[mt][1], a[mt][2], a[mt][3], addr);
            }
            uint32_t bfr[4][2];
            #pragma unroll
            for (int p = 0; p < 2; p++) {
                uint32_t addr = bb + rbB[p] + 16u * (uint32_t)(((s << 1) + lB_kh) ^ xr);
                ldmatrix_x4(bfr[2*p][0], bfr[2*p][1], bfr[2*p+1][0], bfr[2*p+1][1], addr);
            }
            #pragma unroll
            for (int mt = 0; mt < 4; mt++)
                #pragma unroll
                for (int nt = 0; nt < 4; nt++)
                    mma_bf16(acc[mt][nt], a[mt], bfr[nt]);
        }
        __syncthreads();
    }

    int g = lane >> 2;
    int t2 = (lane & 3) * 2;
    #pragma unroll
    for (int mt = 0; mt < 4; mt++) {
        int row0 = n0 + wr * 64 + mt * 16 + g;
        #pragma unroll
        for (int nt = 0; nt < 4; nt++) {
            int col = m0 + wc * 32 + nt * 8 + t2;
            float b0 = 0.0f, b1 = 0.0f;
            if (dd.bias) { b0 = dd.bias[col]; b1 = dd.bias[col + 1]; }
            float2 v0 = make_float2(acc[mt][nt][0] + b0, acc[mt][nt][1] + b1);
            float2 v1 = make_float2(acc[mt][nt][2] + b0, acc[mt][nt][3] + b1);
            *(float2*)(dd.C + (size_t)row0 * dd.M + col) = v0;
            *(float2*)(dd.C + (size_t)(row0 + 8) * dd.M + col) = v1;
        }
    }
}

// =====================================================================
// GRU epilogue (device body + batched desc)
// =====================================================================
struct EDesc {
    const float* gi; const float* gh; const float* h; float* out;
    int N; int D; int mode; const float* qmask; int start;
};
struct EBatch { EDesc d[2]; int nd; };

__device__ __forceinline__ void epi_elem(const EDesc& dd, int idx)
{
    if (idx >= dd.N * dd.D) return;
    int n = idx / dd.D;
    int j = idx - n * dd.D;
    int D = dd.D;
    int gn = (dd.mode == 1) ? (n >> 1) : n;
    size_t gib = (size_t)gn * 3 * D + j;
    size_t ghb = (size_t)n * 3 * D + j;
    float ir = dd.gi[gib],          hr = dd.gh[ghb];
    float iz = dd.gi[gib + D],      hz = dd.gh[ghb + D];
    float in_ = dd.gi[gib + 2 * D], hn = dd.gh[ghb + 2 * D];
    float r = 1.0f / (1.0f + __expf(-(ir + hr)));
    float z = 1.0f / (1.0f + __expf(-(iz + hz)));
    float nn = tanhf(in_ + r * hn);
    float hv = dd.h[idx];
    float val = (1.0f - z) * nn + z * hv;
    if (dd.mode == 1) {
        float qm = dd.qmask[n];
        val = hv * (1.0f - qm) + val * qm;
    }
    dd.out[idx] = val;
}

__device__ __forceinline__ void epi_body(const EBatch& eb, int blk)
{
    int di = (eb.nd > 1 && blk >= eb.d[1].start) ? 1 : 0;
    const EDesc dd = eb.d[di];
    epi_elem(dd, (blk - dd.start) * 256 + threadIdx.x);
}

__global__ void gru_epi(const float* __restrict__ gi, const float* __restrict__ gh,
                        const float* __restrict__ h, float* __restrict__ out,
                        int N, int D, int mode, const float* __restrict__ qmask)
{
    EDesc dd = { gi, gh, h, out, N, D, mode, qmask, 0 };
    epi_elem(dd, blockIdx.x * 256 + threadIdx.x);
}

// =====================================================================
// Fused heterogeneous launch: gemm (interleaved) | attn_g | attn_q | epi
// =====================================================================
__global__ __launch_bounds__(256, 2) void fused_all(
    TBatch tb, EBatch eb, int n_gemm, int n_attn_g, int n_attn_q,
    const float* __restrict__ g_hist, const float* __restrict__ w_att,
    float* __restrict__ c_out, float* __restrict__ alpha_base,
    __nv_bfloat16* __restrict__ xcp_bf,
    const float* __restrict__ q_hist, const float* __restrict__ xt,
    __nv_bfloat16* __restrict__ qc_bf)
{
    extern __shared__ __align__(128) char smem_raw[];
    int widx;
    if (work_map(blockIdx.x, n_gemm, gridDim.x, widx)) {
        mma_gemm_body(tb, smem_raw, widx);
    } else if (widx < n_attn_g) {
        int b = widx;
        attn_body<1>(smem_raw, g_hist, (size_t)Bn * D_G, (size_t)b * D_G,
                     w_att,
                     c_out + (size_t)b * D_G,
                     alpha_base + (size_t)b * Tn,
                     xcp_bf + (size_t)b * 4608 + 1024, 1536);
    } else if (widx < n_attn_g + n_attn_q) {
        int n = widx - n_attn_g;
        attn_body<0>(smem_raw, q_hist, (size_t)Bn * PARTY * D_P, (size_t)n * D_P,
                     xt + (size_t)n * D_P,
                     nullptr, nullptr,
                     qc_bf + (size_t)n * 1536, 512);
    } else {
        epi_body(eb, widx - n_attn_g - n_attn_q);
    }
}

// =====================================================================
// conversions (batched): fp32 -> bf16 hi/lo split, with gather modes.
// mode 0: activation [hi|lo|hi]  mode 1: weight [hi|hi|lo]
// mode 2: XCG gather [U | q0_sel] (activation layout)
// mode 3: E0SW party-swap gather of e0 (activation layout)
// =====================================================================
#define MAXC 13
struct CDesc { const float* in; __nv_bfloat16* out; int Kin; int Kout; int colofs; int total; int start; int mode; };
struct CBatch { CDesc d[MAXC]; int nd; };

__global__ __launch_bounds__(256) void conv_batch(CBatch cb,
    const float* __restrict__ U, const float* __restrict__ qmask,
    const float* __restrict__ q0, const float* __restrict__ e0)
{
    int bid = blockIdx.x;
    int di = 0;
    #pragma unroll
    for (int k = 1; k < MAXC; k++)
        if (k < cb.nd && bid >= cb.d[k].start) di = k;
    const CDesc dd = cb.d[di];
    int base = (bid - dd.start) * 2048 + threadIdx.x;
    #pragma unroll
    for (int i = 0; i < 8; i++) {
        int idx = base + i * 256;
        if (idx >= dd.total) break;
        int r = idx / dd.Kin;
        int k = idx - r * dd.Kin;
        float x;
        if (dd.mode == 2) {
            if (k < D_M) x = U[(size_t)r * D_M + k];
            else {
                int qi = (qmask[r * 2 + 1] > qmask[r * 2 + 0]) ? 1 : 0;
                x = q0[(size_t)(r * 2 + qi) * D_P + (k - D_M)];
            }
        } else if (dd.mode == 3) {
            int b = r >> 1, p = r & 1;
            x = e0[(size_t)(b * 2 + (1 - p)) * D_E + k];
        } else {
            x = dd.in[idx];
        }
        __nv_bfloat16 hi = __float2bfloat16(x);
        __nv_bfloat16 lo = __float2bfloat16(x - __bfloat162float(hi));
        __nv_bfloat16* o = dd.out + (size_t)r * 3 * dd.Kout + dd.colofs + k;
        if (dd.mode == 1) { o[0] = hi; o[dd.Kout] = hi; o[2 * dd.Kout] = lo; }
        else              { o[0] = hi; o[dd.Kout] = lo; o[2 * dd.Kout] = hi; }
    }
}

// =====================================================================
// launch
// =====================================================================
extern "C" void kernel_launch(void* const* d_in, const int* in_sizes, int n_in,
                              void* d_out, int out_size)
{
    const float* U       = (const float*)d_in[0];
    const float* qmask   = (const float*)d_in[1];
    const float* g_hist  = (const float*)d_in[2];
    const float* q0      = (const float*)d_in[3];
    const float* q_hist  = (const float*)d_in[4];
    const float* e0      = (const float*)d_in[5];
    const float* w_ih_g  = (const float*)d_in[6];
    const float* w_hh_g  = (const float*)d_in[7];
    const float* b_ih_g  = (const float*)d_in[8];
    const float* b_hh_g  = (const float*)d_in[9];
    const float* w_ih_p  = (const float*)d_in[10];
    const float* w_hh_p  = (const float*)d_in[11];
    const float* b_ih_p  = (const float*)d_in[12];
    const float* b_hh_p  = (const float*)d_in[13];
    const float* w_ih_e  = (const float*)d_in[14];
    const float* w_hh_e  = (const float*)d_in[15];
    const float* b_ih_e  = (const float*)d_in[16];
    const float* b_hh_e  = (const float*)d_in[17];
    const float* w_att   = (const float*)d_in[18];
    const float* w_trans = (const float*)d_in[19];
    float* out = (float*)d_out;

    static int smem_set = 0;
    if (!smem_set) {
        cudaFuncSetAttribute(fused_all, cudaFuncAttributeMaxDynamicSharedMemorySize, DYN_SMEM_BYTES);
        smem_set = 1;
    }

    float *gi_p, *gie_p, *gh_p, *ghe_p, *ghp_p, *xt_p, *gih_p;
    __nv_bfloat16* bf;
    cudaGetSymbolAddress((void**)&gi_p,   d_gi_buf);
    cudaGetSymbolAddress((void**)&gie_p,  d_gie_buf);
    cudaGetSymbolAddress((void**)&gh_p,   d_gh_buf);
    cudaGetSymbolAddress((void**)&ghe_p,  d_ghe_buf);
    cudaGetSymbolAddress((void**)&ghp_p,  d_ghp_buf);
    cudaGetSymbolAddress((void**)&xt_p,   d_xt_buf);
    cudaGetSymbolAddress((void**)&gih_p,  d_gih_buf);
    cudaGetSymbolAddress((void**)&bf,     d_bf);

    const float* g_last = g_hist + (size_t)(Tn - 1) * Bn * D_G;
    EBatch eb0; eb0.nd = 0;
    eb0.d[0] = { nullptr, nullptr, nullptr, nullptr, 0, 1, 0, nullptr, 0 };
    eb0.d[1] = eb0.d[0];

    // ---- L0: single conv launch (weights + activations + gathers) ----
    {
        CBatch cb; cb.nd = 13;
        int s = 0;
        auto add = [&](int i, const float* in, unsigned long long off,
                       int Kin, int Kout, int colofs, int total, int mode) {
            cb.d[i] = { in, bf + off, Kin, Kout, colofs, total, s, mode };
            s += (total + 2047) / 2048;
        };
        add(0,  w_ih_g,  OFF_WIHG,  1536, 1536, 0, 1536 * 1536, 1);
        add(1,  w_hh_g,  OFF_WHHG,  512,  512,  0, 1536 * 512,  1);
        add(2,  w_ih_p,  OFF_WIHP,  1536, 1536, 0, 1536 * 1536, 1);
        add(3,  w_hh_p,  OFF_WHHP,  512,  512,  0, 1536 * 512,  1);
        add(4,  w_ih_e,  OFF_WIHE,  512,  512,  0, 1536 * 512,  1);
        add(5,  w_hh_e,  OFF_WHHE,  512,  512,  0, 1536 * 512,  1);
        add(6,  w_trans, OFF_WTR,   512,  512,  0, 512 * 512,   1);
        add(7,  nullptr, OFF_XCG,   1536, 1536, 0, 512 * 1536,  2);   // [U|q0_sel] gather
        add(8,  g_last,  OFF_GLAST, 512,  512,  0, 512 * 512,   0);
        add(9,  q0,      OFF_Q0,    512,  512,  0, 1024 * 512,  0);
        add(10, nullptr, OFF_E0SW,  512,  512,  0, 1024 * 512,  3);   // e0 party-swap gather
        add(11, e0,      OFF_E0,    512,  512,  0, 1024 * 512,  0);
        add(12, U,       OFF_XCP,   1024, 1536, 0, 512 * 1024,  0);   // XCP U-columns
        conv_batch<<<s, 256>>>(cb, U, qmask, q0, e0);
    }

    // ---- L1: fused {gi_g, gh_g, gh_p, xt, gh_e} + attn_g (interleaved) ----
    {
        TBatch tb; tb.nd = 5;
        int s = 0;
        tb.d[0] = { bf + OFF_XCG,   bf + OFF_WIHG, b_ih_g, gi_p,  4608, 3 * D_G, 12, s }; s += 48;
        tb.d[1] = { bf + OFF_GLAST, bf + OFF_WHHG, b_hh_g, gh_p,  1536, 3 * D_G, 12, s }; s += 48;
        tb.d[2] = { bf + OFF_Q0,    bf + OFF_WHHP, b_hh_p, ghp_p, 1536, 3 * D_P, 12, s }; s += 96;
        tb.d[3] = { bf + OFF_E0SW,  bf + OFF_WTR,  nullptr, xt_p, 1536, D_P,      4, s }; s += 32;
        tb.d[4] = { bf + OFF_E0,    bf + OFF_WHHE, b_hh_e, ghe_p, 1536, 3 * D_E, 12, s }; s += 96;
        int total = s + Bn;
        fused_all<<<total, 256, DYN_SMEM_BYTES>>>(tb, eb0, s, Bn, 0, g_hist, w_att,
                                                  out + C_OFF, out + A_OFF, bf + OFF_XCP,
                                                  q_hist, xt_p, bf + OFF_QC);
    }

    // ---- L2: fused {gi_p} + attn_q (interleaved) ----
    {
        TBatch tb; tb.nd = 1;
        tb.d[0] = { bf + OFF_XCP, bf + OFF_WIHP, b_ih_p, gih_p, 4608, 3 * D_P, 12, 0 };
        int s = 48;
        int total = s + Bn * PARTY;
        fused_all<<<total, 256, DYN_SMEM_BYTES>>>(tb, eb0, s, 0, Bn * PARTY, g_hist, w_att,
                                                  nullptr, nullptr, nullptr,
                                                  q_hist, xt_p, bf + OFF_QC);
    }

    // ---- L3: fused {gi_e} + epilogues g, p (interleaved) ----
    {
        TBatch tb; tb.nd = 1;
        tb.d[0] = { bf + OFF_QC, bf + OFF_WIHE, b_ih_e, gie_p, 1536, 3 * D_E, 12, 0 };
        int s = 96;
        EBatch eb; eb.nd = 2;
        int epi_g_blocks = (Bn * D_G + 255) / 256;             // 1024
        int epi_p_blocks = (Bn * PARTY * D_P + 255) / 256;     // 2048
        eb.d[0] = { gi_p,  gh_p,  g_last, out + G_OFF, Bn,         D_G, 0, nullptr, 0 };
        eb.d[1] = { gih_p, ghp_p, q0,     out + Q_OFF, Bn * PARTY, D_P, 1, qmask, epi_g_blocks };
        int total = s + epi_g_blocks + epi_p_blocks;
        fused_all<<<total, 256, DYN_SMEM_BYTES>>>(tb, eb, s, 0, 0, g_hist, w_att,
                                                  nullptr, nullptr, nullptr,
                                                  q_hist, xt_p, bf + OFF_QC);
    }

    // ---- L4: epilogue e ----
    gru_epi<<<(Bn * PARTY * D_E + 255) / 256, 256>>>(gie_p, ghe_p, e0, out + E_OFF,
                                                     Bn * PARTY, D_E, 0, nullptr);
}

// round 12
// speedup vs baseline: 1.0027x; 1.0027x over previous
#include <cuda_runtime.h>
#include <cuda_bf16.h>
#include <math.h>
#include <stdint.h>

#define Bn 512
#define Tn 200
#define PARTY 2
#define D_M 1024
#define D_G 512
#define D_P 512
#define D_E 512

// Output layout (flattened tuple): g_, q_, e_, c_, alpha_out
#define G_OFF 0
#define Q_OFF (Bn * D_G)
#define E_OFF (Q_OFF + Bn * PARTY * D_P)
#define C_OFF (E_OFF + Bn * PARTY * D_E)
#define A_OFF (C_OFF + Bn * D_G)

// ---------------- fp32 scratch ----------------
__device__ float d_gi_buf[(Bn * PARTY) * 3 * D_G];    // gi_g (512 rows used)
__device__ float d_gie_buf[(Bn * PARTY) * 3 * D_E];   // gi_e (dedicated, avoids race)
__device__ float d_gh_buf[Bn * 3 * D_G];              // gh_g
__device__ float d_ghe_buf[(Bn * PARTY) * 3 * D_E];   // gh_e
__device__ float d_ghp_buf[(Bn * PARTY) * 3 * D_P];   // gh_p
__device__ float d_xt_buf[Bn * PARTY * D_P];
__device__ float d_gih_buf[Bn * 3 * D_P];             // gi_p dedup

// ---------------- bf16 split scratch (hi/lo concat, K tripled) ----------------
#define OFF_WIHG  0ull                       // 1536 x 4608
#define OFF_WHHG  (OFF_WIHG  + 7077888ull)   // 1536 x 1536
#define OFF_WIHP  (OFF_WHHG  + 2359296ull)   // 1536 x 4608
#define OFF_WHHP  (OFF_WIHP  + 7077888ull)   // 1536 x 1536
#define OFF_WIHE  (OFF_WHHP  + 2359296ull)   // 1536 x 1536
#define OFF_WHHE  (OFF_WIHE  + 2359296ull)   // 1536 x 1536
#define OFF_WTR   (OFF_WHHE  + 2359296ull)   // 512 x 1536
#define OFF_XCG   (OFF_WTR   + 786432ull)    // 512 x 4608 (gather-conv from U/qmask/q0)
#define OFF_GLAST (OFF_XCG   + 2359296ull)   // 512 x 1536
#define OFF_Q0    (OFF_GLAST + 786432ull)    // 1024 x 1536
#define OFF_E0SW  (OFF_Q0    + 1572864ull)   // 1024 x 1536 (gather-conv from e0)
#define OFF_E0    (OFF_E0SW  + 1572864ull)   // 1024 x 1536
#define OFF_XCP   (OFF_E0    + 1572864ull)   // 512 x 4608 (U-cols by conv; c_-cols by attn_g)
#define OFF_QC    (OFF_XCP   + 2359296ull)   // 1024 x 1536 (by attn_q)
#define BF_TOTAL  (OFF_QC    + 1572864ull)
__device__ __align__(16) __nv_bfloat16 d_bf[BF_TOTAL];

// =====================================================================
// helpers
// =====================================================================
__device__ __forceinline__ uint32_t smem_u32(const void* p) {
    uint32_t r;
    asm("{ .reg .u64 t; cvta.to.shared.u64 t, %1; cvt.u32.u64 %0, t; }" : "=r"(r) : "l"(p));
    return r;
}
__device__ __forceinline__ void cp_async16(uint32_t dst, const void* src) {
    asm volatile("cp.async.cg.shared.global [%0], [%1], 16;" :: "r"(dst), "l"(src) : "memory");
}
__device__ __forceinline__ void cp_commit() {
    asm volatile("cp.async.commit_group;" ::: "memory");
}
template<int N>
__device__ __forceinline__ void cp_wait() {
    asm volatile("cp.async.wait_group %0;" :: "n"(N) : "memory");
}
__device__ __forceinline__ void ldmatrix_x4(uint32_t& r0, uint32_t& r1, uint32_t& r2, uint32_t& r3,
                                            uint32_t addr) {
    asm volatile("ldmatrix.sync.aligned.m8n8.x4.shared.b16 {%0,%1,%2,%3}, [%4];"
                 : "=r"(r0), "=r"(r1), "=r"(r2), "=r"(r3) : "r"(addr));
}
__device__ __forceinline__ void mma_bf16(float* d, const uint32_t* a, const uint32_t* b) {
    asm volatile("mma.sync.aligned.m16n8k16.row.col.f32.bf16.bf16.f32 "
                 "{%0,%1,%2,%3}, {%4,%5,%6,%7}, {%8,%9}, {%0,%1,%2,%3};"
                 : "+f"(d[0]), "+f"(d[1]), "+f"(d[2]), "+f"(d[3])
                 : "r"(a[0]), "r"(a[1]), "r"(a[2]), "r"(a[3]), "r"(b[0]), "r"(b[1]));
}
__device__ __forceinline__ void lds128(float* v, uint32_t addr) {
    asm volatile("ld.shared.v4.f32 {%0,%1,%2,%3}, [%4];"
                 : "=f"(v[0]), "=f"(v[1]), "=f"(v[2]), "=f"(v[3]) : "r"(addr));
}
__device__ __forceinline__ void split3(float x, __nv_bfloat16* o, int stride) {
    __nv_bfloat16 hi = __float2bfloat16(x);
    __nv_bfloat16 lo = __float2bfloat16(x - __bfloat162float(hi));
    o[0] = hi; o[stride] = lo; o[2 * stride] = hi;
}
// proportional interleave: spread ng gemm blocks uniformly over total
__device__ __forceinline__ bool work_map(int bid, int ng, int total, int& widx) {
    long long p0 = ((long long)bid * ng) / total;
    long long p1 = ((long long)(bid + 1) * ng) / total;
    if (p1 > p0) { widx = (int)p0; return true; }
    widx = bid - (int)p0; return false;
}

// =====================================================================
// Attention body: per-warp online softmax, 3-deep cp.async staging.
// Smem: [tile0|tile1|tile2 16KB each][AttnSmem]
// =====================================================================
struct AttnSmem {
    float m[8]; float s[8]; float w8[8];
    float Mg, Sg;
    float sc[Tn];
    float acc[8][512];
};
#define ATTN_TILE_BYTES 16384
#define ATTN_SM_OFF (3 * ATTN_TILE_BYTES)

template<int MODE>
__device__ __forceinline__ void attn_body(
    char* smem_raw,
    const float* __restrict__ hist, size_t tstride, size_t row_off,
    const float* __restrict__ wvec,
    float* __restrict__ c_out,
    float* __restrict__ alpha_out,
    __nv_bfloat16* __restrict__ bf_out,
    int bf_stride)
{
    uint32_t sb = smem_u32(smem_raw);
    AttnSmem* sm = reinterpret_cast<AttnSmem*>(smem_raw + ATTN_SM_OFF);
    int tid = threadIdx.x;
    int lane = tid & 31;
    int w = tid >> 5;

    const float* src = hist + row_off;

    int trow_[4], c16_[4];
    #pragma unroll
    for (int i = 0; i < 4; i++) {
        int u = tid + 256 * i;
        trow_[i] = u >> 7;
        c16_[i] = u & 127;
    }

    float q[16];
    #pragma unroll
    for (int j = 0; j < 4; j++) {
        float4 t4 = *(const float4*)(wvec + lane * 4 + j * 128);
        q[j*4+0] = t4.x; q[j*4+1] = t4.y; q[j*4+2] = t4.z; q[j*4+3] = t4.w;
    }

    float m = -INFINITY, s = 0.0f;
    float acc[16];
    #pragma unroll
    for (int k = 0; k < 16; k++) acc[k] = 0.0f;

    // prologue: chunks 0..2
    #pragma unroll
    for (int c = 0; c < 3; c++) {
        uint32_t dst = sb + (uint32_t)c * ATTN_TILE_BYTES;
        #pragma unroll
        for (int i = 0; i < 4; i++) {
            cp_async16(dst + (uint32_t)(trow_[i] * 2048 + c16_[i] * 16),
                       src + (size_t)(c * 8 + trow_[i]) * tstride + c16_[i] * 4);
        }
        cp_commit();
    }

    int buf = 0;
    for (int i = 0; i < 25; i++) {
        if (i < 23) cp_wait<2>(); else if (i == 23) cp_wait<1>(); else cp_wait<0>();
        __syncthreads();

        uint32_t vbase = sb + (uint32_t)buf * ATTN_TILE_BYTES + (uint32_t)(w * 2048 + lane * 16);
        float v[16];
        #pragma unroll
        for (int j = 0; j < 4; j++) lds128(v + j * 4, vbase + j * 512);

        int t = i * 8 + w;
        float dot = 0.0f;
        #pragma unroll
        for (int k = 0; k < 16; k++) dot = fmaf(v[k], q[k], dot);
        #pragma unroll
        for (int o = 16; o > 0; o >>= 1) dot += __shfl_xor_sync(0xffffffffu, dot, o);

        if (MODE == 1 && lane == 0) sm->sc[t] = dot;

        float nm = fmaxf(m, dot);
        float rs = __expf(m - nm);
        float cf = __expf(dot - nm);
        #pragma unroll
        for (int k = 0; k < 16; k++) acc[k] = fmaf(acc[k], rs, cf * v[k]);
        s = fmaf(s, rs, cf);
        m = nm;

        __syncthreads();
        if (i + 3 < 25) {
            uint32_t dst = sb + (uint32_t)buf * ATTN_TILE_BYTES;
            #pragma unroll
            for (int j = 0; j < 4; j++) {
                cp_async16(dst + (uint32_t)(trow_[j] * 2048 + c16_[j] * 16),
                           src + (size_t)((i + 3) * 8 + trow_[j]) * tstride + c16_[j] * 4);
            }
            cp_commit();
        }
        buf = (buf == 2) ? 0 : buf + 1;
    }

    if (lane == 0) { sm->m[w] = m; sm->s[w] = s; }
    #pragma unroll
    for (int j = 0; j < 4; j++)
        #pragma unroll
        for (int u = 0; u < 4; u++)
            sm->acc[w][lane * 4 + j * 128 + u] = acc[j*4+u];
    __syncthreads();

    if (tid == 0) {
        float M = -INFINITY;
        #pragma unroll
        for (int k = 0; k < 8; k++) M = fmaxf(M, sm->m[k]);
        float S = 0.0f;
        #pragma unroll
        for (int k = 0; k < 8; k++) S += sm->s[k] * __expf(sm->m[k] - M);
        float invS = 1.0f / S;
        #pragma unroll
        for (int k = 0; k < 8; k++) sm->w8[k] = __expf(sm->m[k] - M) * invS;
        sm->Mg = M; sm->Sg = S;
    }
    __syncthreads();

    int c = tid * 2;
    float o0 = 0.0f, o1 = 0.0f;
    #pragma unroll
    for (int k = 0; k < 8; k++) {
        float wk = sm->w8[k];
        o0 = fmaf(sm->acc[k][c], wk, o0);
        o1 = fmaf(sm->acc[k][c + 1], wk, o1);
    }
    if (MODE == 1) {
        *(float2*)(c_out + c) = make_float2(o0, o1);
        split3(o0, bf_out + c,     bf_stride);
        split3(o1, bf_out + c + 1, bf_stride);
        if (tid < Tn) {
            float inv = 1.0f / sm->Sg;
            alpha_out[tid] = __expf(sm->sc[tid] - sm->Mg) * inv;
        }
    } else {
        split3(o0, bf_out + c,     bf_stride);
        split3(o1, bf_out + c + 1, bf_stride);
    }
}

// =====================================================================
// bf16 mma.sync GEMM body (R7-proven)
// =====================================================================
#define MAXT 5
struct TDesc {
    const __nv_bfloat16* A; const __nv_bfloat16* W;
    const float* bias; float* C;
    int K3; int M; int gridX; int start;
};
struct TBatch { TDesc d[MAXT]; int nd; };

#define DYN_SMEM_BYTES 66560

__device__ __forceinline__ void mma_gemm_body(const TBatch& tb, char* smem_raw, int bid)
{
    int tid = threadIdx.x;
    int wid = tid >> 5;
    int lane = tid & 31;

    int di = 0;
    #pragma unroll
    for (int k = 1; k < MAXT; k++)
        if (k < tb.nd && bid >= tb.d[k].start) di = k;
    const TDesc dd = tb.d[di];
    int local = bid - dd.start;
    int m0 = (local % dd.gridX) * 128;
    int n0 = (local / dd.gridX) * 128;
    const int K3 = dd.K3;
    const int nc = K3 >> 6;

    uint32_t sb = smem_u32(smem_raw);

    int lrow[4], lc16[4]; uint32_t swoff[4];
    #pragma unroll
    for (int i = 0; i < 4; i++) {
        int u = tid + 256 * i;
        int r = u >> 3, c16 = u & 7;
        lrow[i] = r; lc16[i] = c16;
        swoff[i] = (uint32_t)(r * 128 + 16 * (c16 ^ (r & 7)));
    }
    const __nv_bfloat16* Ab = dd.A + (size_t)n0 * K3;
    const __nv_bfloat16* Wb = dd.W + (size_t)m0 * K3;

    int xr = lane & 7;
    int lA_row = (lane & 7) + ((lane >> 3) & 1) * 8;
    int lA_kh = lane >> 4;
    int lB_row = (lane & 7) + (lane >> 4) * 8;
    int lB_kh = (lane >> 3) & 1;
    int wr = wid & 1;
    int wc = wid >> 1;
    uint32_t rbA[4], rbB[2];
    #pragma unroll
    for (int mt = 0; mt < 4; mt++) rbA[mt] = (uint32_t)((wr * 64 + mt * 16 + lA_row) * 128);
    #pragma unroll
    for (int p = 0; p < 2; p++) rbB[p] = (uint32_t)((wc * 32 + p * 16 + lB_row) * 128);

    float acc[4][4][4];
    #pragma unroll
    for (int mt = 0; mt < 4; mt++)
        #pragma unroll
        for (int nt = 0; nt < 4; nt++)
            #pragma unroll
            for (int r = 0; r < 4; r++) acc[mt][nt][r] = 0.0f;

    {
        uint32_t ba = sb, bb = sb + 16384u;
        #pragma unroll
        for (int i = 0; i < 4; i++) {
            cp_async16(ba + swoff[i], Ab + (size_t)lrow[i] * K3 + lc16[i] * 8);
            cp_async16(bb + swoff[i], Wb + (size_t)lrow[i] * K3 + lc16[i] * 8);
        }
        cp_commit();
    }

    for (int c = 0; c < nc; c++) {
        if (c + 1 < nc) {
            uint32_t ba = sb + (uint32_t)((c + 1) & 1) * 32768u;
            uint32_t bb = ba + 16384u;
            int koff = (c + 1) * 64;
            #pragma unroll
            for (int i = 0; i < 4; i++) {
                cp_async16(ba + swoff[i], Ab + (size_t)lrow[i] * K3 + koff + lc16[i] * 8);
                cp_async16(bb + swoff[i], Wb + (size_t)lrow[i] * K3 + koff + lc16[i] * 8);
            }
            cp_commit();
            cp_wait<1>();
        } else {
            cp_wait<0>();
        }
        __syncthreads();

        uint32_t ba = sb + (uint32_t)(c & 1) * 32768u;
        uint32_t bb = ba + 16384u;
        #pragma unroll
        for (int s = 0; s < 4; s++) {
            uint32_t a[4][4];
            #pragma unroll
            for (int mt = 0; mt < 4; mt++) {
                uint32_t addr = ba + rbA[mt] + 16u * (uint32_t)(((s << 1) + lA_kh) ^ xr);
                ldmatrix_x4(a[mt][0], a[mt][1], a[mt][2], a[mt][3], addr);
            }
            uint32_t bfr[4][2];
            #pragma unroll
            for (int p = 0; p < 2; p++) {
                uint32_t addr = bb + rbB[p] + 16u * (uint32_t)(((s << 1) + lB_kh) ^ xr);
                ldmatrix_x4(bfr[2*p][0], bfr[2*p][1], bfr[2*p+1][0], bfr[2*p+1][1], addr);
            }
            #pragma unroll
            for (int mt = 0; mt < 4; mt++)
                #pragma unroll
                for (int nt = 0; nt < 4; nt++)
                    mma_bf16(acc[mt][nt], a[mt], bfr[nt]);
        }
        __syncthreads();
    }

    int g = lane >> 2;
    int t2 = (lane & 3) * 2;
    #pragma unroll
    for (int mt = 0; mt < 4; mt++) {
        int row0 = n0 + wr * 64 + mt * 16 + g;
        #pragma unroll
        for (int nt = 0; nt < 4; nt++) {
            int col = m0 + wc * 32 + nt * 8 + t2;
            float b0 = 0.0f, b1 = 0.0f;
            if (dd.bias) { b0 = dd.bias[col]; b1 = dd.bias[col + 1]; }
            float2 v0 = make_float2(acc[mt][nt][0] + b0, acc[mt][nt][1] + b1);
            float2 v1 = make_float2(acc[mt][nt][2] + b0, acc[mt][nt][3] + b1);
            *(float2*)(dd.C + (size_t)row0 * dd.M + col) = v0;
            *(float2*)(dd.C + (size_t)(row0 + 8) * dd.M + col) = v1;
        }
    }
}

// =====================================================================
// GRU epilogue (device body + batched desc)
// =====================================================================
struct EDesc {
    const float* gi; const float* gh; const float* h; float* out;
    int N; int D; int mode; const float* qmask; int start;
};
struct EBatch { EDesc d[2]; int nd; };

__device__ __forceinline__ void epi_elem(const EDesc& dd, int idx)
{
    if (idx >= dd.N * dd.D) return;
    int n = idx / dd.D;
    int j = idx - n * dd.D;
    int D = dd.D;
    int gn = (dd.mode == 1) ? (n >> 1) : n;
    size_t gib = (size_t)gn * 3 * D + j;
    size_t ghb = (size_t)n * 3 * D + j;
    float ir = dd.gi[gib],          hr = dd.gh[ghb];
    float iz = dd.gi[gib + D],      hz = dd.gh[ghb + D];
    float in_ = dd.gi[gib + 2 * D], hn = dd.gh[ghb + 2 * D];
    float r = 1.0f / (1.0f + __expf(-(ir + hr)));
    float z = 1.0f / (1.0f + __expf(-(iz + hz)));
    float nn = tanhf(in_ + r * hn);
    float hv = dd.h[idx];
    float val = (1.0f - z) * nn + z * hv;
    if (dd.mode == 1) {
        float qm = dd.qmask[n];
        val = hv * (1.0f - qm) + val * qm;
    }
    dd.out[idx] = val;
}

__device__ __forceinline__ void epi_body(const EBatch& eb, int blk)
{
    int di = (eb.nd > 1 && blk >= eb.d[1].start) ? 1 : 0;
    const EDesc dd = eb.d[di];
    epi_elem(dd, (blk - dd.start) * 256 + threadIdx.x);
}

__global__ void gru_epi(const float* __restrict__ gi, const float* __restrict__ gh,
                        const float* __restrict__ h, float* __restrict__ out,
                        int N, int D, int mode, const float* __restrict__ qmask)
{
    EDesc dd = { gi, gh, h, out, N, D, mode, qmask, 0 };
    epi_elem(dd, blockIdx.x * 256 + threadIdx.x);
}

// =====================================================================
// Fused heterogeneous launch: gemm (interleaved) | attn_g | attn_q | epi
// =====================================================================
__global__ __launch_bounds__(256, 2) void fused_all(
    TBatch tb, EBatch eb, int n_gemm, int n_attn_g, int n_attn_q,
    const float* __restrict__ g_hist, const float* __restrict__ w_att,
    float* __restrict__ c_out, float* __restrict__ alpha_base,
    __nv_bfloat16* __restrict__ xcp_bf,
    const float* __restrict__ q_hist, const float* __restrict__ xt,
    __nv_bfloat16* __restrict__ qc_bf)
{
    extern __shared__ __align__(128) char smem_raw[];
    int widx;
    if (work_map(blockIdx.x, n_gemm, gridDim.x, widx)) {
        mma_gemm_body(tb, smem_raw, widx);
    } else if (widx < n_attn_g) {
        int b = widx;
        attn_body<1>(smem_raw, g_hist, (size_t)Bn * D_G, (size_t)b * D_G,
                     w_att,
                     c_out + (size_t)b * D_G,
                     alpha_base + (size_t)b * Tn,
                     xcp_bf + (size_t)b * 4608 + 1024, 1536);
    } else if (widx < n_attn_g + n_attn_q) {
        int n = widx - n_attn_g;
        attn_body<0>(smem_raw, q_hist, (size_t)Bn * PARTY * D_P, (size_t)n * D_P,
                     xt + (size_t)n * D_P,
                     nullptr, nullptr,
                     qc_bf + (size_t)n * 1536, 512);
    } else {
        epi_body(eb, widx - n_attn_g - n_attn_q);
    }
}

// =====================================================================
// conversions (batched): fp32 -> bf16 hi/lo split, with gather modes.
// mode 0: activation [hi|lo|hi]  mode 1: weight [hi|hi|lo]
// mode 2: XCG gather [U | q0_sel] (activation layout)
// mode 3: E0SW party-swap gather of e0 (activation layout)
// =====================================================================
#define MAXC 13
struct CDesc { const float* in; __nv_bfloat16* out; int Kin; int Kout; int colofs; int total; int start; int mode; };
struct CBatch { CDesc d[MAXC]; int nd; };

__global__ __launch_bounds__(256) void conv_batch(CBatch cb,
    const float* __restrict__ U, const float* __restrict__ qmask,
    const float* __restrict__ q0, const float* __restrict__ e0)
{
    int bid = blockIdx.x;
    int di = 0;
    #pragma unroll
    for (int k = 1; k < MAXC; k++)
        if (k < cb.nd && bid >= cb.d[k].start) di = k;
    const CDesc dd = cb.d[di];
    int base = (bid - dd.start) * 2048 + threadIdx.x;
    #pragma unroll
    for (int i = 0; i < 8; i++) {
        int idx = base + i * 256;
        if (idx >= dd.total) break;
        int r = idx / dd.Kin;
        int k = idx - r * dd.Kin;
        float x;
        if (dd.mode == 2) {
            if (k < D_M) x = U[(size_t)r * D_M + k];
            else {
                int qi = (qmask[r * 2 + 1] > qmask[r * 2 + 0]) ? 1 : 0;
                x = q0[(size_t)(r * 2 + qi) * D_P + (k - D_M)];
            }
        } else if (dd.mode == 3) {
            int b = r >> 1, p = r & 1;
            x = e0[(size_t)(b * 2 + (1 - p)) * D_E + k];
        } else {
            x = dd.in[idx];
        }
        __nv_bfloat16 hi = __float2bfloat16(x);
        __nv_bfloat16 lo = __float2bfloat16(x - __bfloat162float(hi));
        __nv_bfloat16* o = dd.out + (size_t)r * 3 * dd.Kout + dd.colofs + k;
        if (dd.mode == 1) { o[0] = hi; o[dd.Kout] = hi; o[2 * dd.Kout] = lo; }
        else              { o[0] = hi; o[dd.Kout] = lo; o[2 * dd.Kout] = hi; }
    }
}

// =====================================================================
// launch
// =====================================================================
extern "C" void kernel_launch(void* const* d_in, const int* in_sizes, int n_in,
                              void* d_out, int out_size)
{
    const float* U       = (const float*)d_in[0];
    const float* qmask   = (const float*)d_in[1];
    const float* g_hist  = (const float*)d_in[2];
    const float* q0      = (const float*)d_in[3];
    const float* q_hist  = (const float*)d_in[4];
    const float* e0      = (const float*)d_in[5];
    const float* w_ih_g  = (const float*)d_in[6];
    const float* w_hh_g  = (const float*)d_in[7];
    const float* b_ih_g  = (const float*)d_in[8];
    const float* b_hh_g  = (const float*)d_in[9];
    const float* w_ih_p  = (const float*)d_in[10];
    const float* w_hh_p  = (const float*)d_in[11];
    const float* b_ih_p  = (const float*)d_in[12];
    const float* b_hh_p  = (const float*)d_in[13];
    const float* w_ih_e  = (const float*)d_in[14];
    const float* w_hh_e  = (const float*)d_in[15];
    const float* b_ih_e  = (const float*)d_in[16];
    const float* b_hh_e  = (const float*)d_in[17];
    const float* w_att   = (const float*)d_in[18];
    const float* w_trans = (const float*)d_in[19];
    float* out = (float*)d_out;

    static int smem_set = 0;
    if (!smem_set) {
        cudaFuncSetAttribute(fused_all, cudaFuncAttributeMaxDynamicSharedMemorySize, DYN_SMEM_BYTES);
        smem_set = 1;
    }

    float *gi_p, *gie_p, *gh_p, *ghe_p, *ghp_p, *xt_p, *gih_p;
    __nv_bfloat16* bf;
    cudaGetSymbolAddress((void**)&gi_p,   d_gi_buf);
    cudaGetSymbolAddress((void**)&gie_p,  d_gie_buf);
    cudaGetSymbolAddress((void**)&gh_p,   d_gh_buf);
    cudaGetSymbolAddress((void**)&ghe_p,  d_ghe_buf);
    cudaGetSymbolAddress((void**)&ghp_p,  d_ghp_buf);
    cudaGetSymbolAddress((void**)&xt_p,   d_xt_buf);
    cudaGetSymbolAddress((void**)&gih_p,  d_gih_buf);
    cudaGetSymbolAddress((void**)&bf,     d_bf);

    const float* g_last = g_hist + (size_t)(Tn - 1) * Bn * D_G;
    EBatch eb0; eb0.nd = 0;
    eb0.d[0] = { nullptr, nullptr, nullptr, nullptr, 0, 1, 0, nullptr, 0 };
    eb0.d[1] = eb0.d[0];

    // ---- L0: single conv launch (weights + activations + gathers) ----
    {
        CBatch cb; cb.nd = 13;
        int s = 0;
        auto add = [&](int i, const float* in, unsigned long long off,
                       int Kin, int Kout, int colofs, int total, int mode) {
            cb.d[i] = { in, bf + off, Kin, Kout, colofs, total, s, mode };
            s += (total + 2047) / 2048;
        };
        add(0,  w_ih_g,  OFF_WIHG,  1536, 1536, 0, 1536 * 1536, 1);
        add(1,  w_hh_g,  OFF_WHHG,  512,  512,  0, 1536 * 512,  1);
        add(2,  w_ih_p,  OFF_WIHP,  1536, 1536, 0, 1536 * 1536, 1);
        add(3,  w_hh_p,  OFF_WHHP,  512,  512,  0, 1536 * 512,  1);
        add(4,  w_ih_e,  OFF_WIHE,  512,  512,  0, 1536 * 512,  1);
        add(5,  w_hh_e,  OFF_WHHE,  512,  512,  0, 1536 * 512,  1);
        add(6,  w_trans, OFF_WTR,   512,  512,  0, 512 * 512,   1);
        add(7,  nullptr, OFF_XCG,   1536, 1536, 0, 512 * 1536,  2);   // [U|q0_sel] gather
        add(8,  g_last,  OFF_GLAST, 512,  512,  0, 512 * 512,   0);
        add(9,  q0,      OFF_Q0,    512,  512,  0, 1024 * 512,  0);
        add(10, nullptr, OFF_E0SW,  512,  512,  0, 1024 * 512,  3);   // e0 party-swap gather
        add(11, e0,      OFF_E0,    512,  512,  0, 1024 * 512,  0);
        add(12, U,       OFF_XCP,   1024, 1536, 0, 512 * 1024,  0);   // XCP U-columns
        conv_batch<<<s, 256>>>(cb, U, qmask, q0, e0);
    }

    // ---- L1: fused {gi_g, gh_g, gh_p, xt, gh_e} + attn_g (interleaved) ----
    {
        TBatch tb; tb.nd = 5;
        int s = 0;
        tb.d[0] = { bf + OFF_XCG,   bf + OFF_WIHG, b_ih_g, gi_p,  4608, 3 * D_G, 12, s }; s += 48;
        tb.d[1] = { bf + OFF_GLAST, bf + OFF_WHHG, b_hh_g, gh_p,  1536, 3 * D_G, 12, s }; s += 48;
        tb.d[2] = { bf + OFF_Q0,    bf + OFF_WHHP, b_hh_p, ghp_p, 1536, 3 * D_P, 12, s }; s += 96;
        tb.d[3] = { bf + OFF_E0SW,  bf + OFF_WTR,  nullptr, xt_p, 1536, D_P,      4, s }; s += 32;
        tb.d[4] = { bf + OFF_E0,    bf + OFF_WHHE, b_hh_e, ghe_p, 1536, 3 * D_E, 12, s }; s += 96;
        int total = s + Bn;
        fused_all<<<total, 256, DYN_SMEM_BYTES>>>(tb, eb0, s, Bn, 0, g_hist, w_att,
                                                  out + C_OFF, out + A_OFF, bf + OFF_XCP,
                                                  q_hist, xt_p, bf + OFF_QC);
    }

    // ---- L2: fused {gi_p} + attn_q (interleaved) ----
    {
        TBatch tb; tb.nd = 1;
        tb.d[0] = { bf + OFF_XCP, bf + OFF_WIHP, b_ih_p, gih_p, 4608, 3 * D_P, 12, 0 };
        int s = 48;
        int total = s + Bn * PARTY;
        fused_all<<<total, 256, DYN_SMEM_BYTES>>>(tb, eb0, s, 0, Bn * PARTY, g_hist, w_att,
                                                  nullptr, nullptr, nullptr,
                                                  q_hist, xt_p, bf + OFF_QC);
    }

    // ---- L3: fused {gi_e} + epilogues g, p (interleaved) ----
    {
        TBatch tb; tb.nd = 1;
        tb.d[0] = { bf + OFF_QC, bf + OFF_WIHE, b_ih_e, gie_p, 1536, 3 * D_E, 12, 0 };
        int s = 96;
        EBatch eb; eb.nd = 2;
        int epi_g_blocks = (Bn * D_G + 255) / 256;             // 1024
        int epi_p_blocks = (Bn * PARTY * D_P + 255) / 256;     // 2048
        eb.d[0] = { gi_p,  gh_p,  g_last, out + G_OFF, Bn,         D_G, 0, nullptr, 0 };
        eb.d[1] = { gih_p, ghp_p, q0,     out + Q_OFF, Bn * PARTY, D_P, 1, qmask, epi_g_blocks };
        int total = s + epi_g_blocks + epi_p_blocks;
        fused_all<<<total, 256, DYN_SMEM_BYTES>>>(tb, eb, s, 0, 0, g_hist, w_att,
                                                  nullptr, nullptr, nullptr,
                                                  q_hist, xt_p, bf + OFF_QC);
    }

    // ---- L4: epilogue e ----
    gru_epi<<<(Bn * PARTY * D_E + 255) / 256, 256>>>(gie_p, ghe_p, e0, out + E_OFF,
                                                     Bn * PARTY, D_E, 0, nullptr);
}

// round 13
// speedup vs baseline: 1.0965x; 1.0935x over previous
#include <cuda_runtime.h>
#include <cuda_bf16.h>
#include <math.h>
#include <stdint.h>

#define Bn 512
#define Tn 200
#define PARTY 2
#define D_M 1024
#define D_G 512
#define D_P 512
#define D_E 512

// Output layout (flattened tuple): g_, q_, e_, c_, alpha_out
#define G_OFF 0
#define Q_OFF (Bn * D_G)
#define E_OFF (Q_OFF + Bn * PARTY * D_P)
#define C_OFF (E_OFF + Bn * PARTY * D_E)
#define A_OFF (C_OFF + Bn * D_G)

// ---------------- fp32 scratch ----------------
__device__ float d_gi_buf[(Bn * PARTY) * 3 * D_G];    // gi_g ; later gi_e
__device__ float d_gh_buf[Bn * 3 * D_G];              // gh_g
__device__ float d_ghe_buf[(Bn * PARTY) * 3 * D_E];   // gh_e
__device__ float d_ghp_buf[(Bn * PARTY) * 3 * D_P];   // gh_p
__device__ float d_xt_buf[Bn * PARTY * D_P];
__device__ float d_gih_buf[Bn * 3 * D_P];             // gi_p dedup

// ---------------- bf16 split scratch (hi/lo concat, K tripled) ----------------
#define OFF_WIHG  0ull                       // 1536 x 4608
#define OFF_WHHG  (OFF_WIHG  + 7077888ull)   // 1536 x 1536
#define OFF_WIHP  (OFF_WHHG  + 2359296ull)   // 1536 x 4608
#define OFF_WHHP  (OFF_WIHP  + 7077888ull)   // 1536 x 1536
#define OFF_WIHE  (OFF_WHHP  + 2359296ull)   // 1536 x 1536
#define OFF_WHHE  (OFF_WIHE  + 2359296ull)   // 1536 x 1536
#define OFF_WTR   (OFF_WHHE  + 2359296ull)   // 512 x 1536
#define OFF_XCG   (OFF_WTR   + 786432ull)    // 512 x 4608 (gather-conv from U/qmask/q0)
#define OFF_GLAST (OFF_XCG   + 2359296ull)   // 512 x 1536
#define OFF_Q0    (OFF_GLAST + 786432ull)    // 1024 x 1536
#define OFF_E0SW  (OFF_Q0    + 1572864ull)   // 1024 x 1536 (gather-conv from e0)
#define OFF_E0    (OFF_E0SW  + 1572864ull)   // 1024 x 1536
#define OFF_XCP   (OFF_E0    + 1572864ull)   // 512 x 4608 (U-cols by conv; c_-cols by attn_g)
#define OFF_QC    (OFF_XCP   + 2359296ull)   // 1024 x 1536 (by attn_q)
#define BF_TOTAL  (OFF_QC    + 1572864ull)
__device__ __align__(16) __nv_bfloat16 d_bf[BF_TOTAL];

// =====================================================================
// helpers
// =====================================================================
__device__ __forceinline__ uint32_t smem_u32(const void* p) {
    uint32_t r;
    asm("{ .reg .u64 t; cvta.to.shared.u64 t, %1; cvt.u32.u64 %0, t; }" : "=r"(r) : "l"(p));
    return r;
}
__device__ __forceinline__ void cp_async16(uint32_t dst, const void* src) {
    asm volatile("cp.async.cg.shared.global [%0], [%1], 16;" :: "r"(dst), "l"(src) : "memory");
}
__device__ __forceinline__ void cp_commit() {
    asm volatile("cp.async.commit_group;" ::: "memory");
}
template<int N>
__device__ __forceinline__ void cp_wait() {
    asm volatile("cp.async.wait_group %0;" :: "n"(N) : "memory");
}
__device__ __forceinline__ void ldmatrix_x4(uint32_t& r0, uint32_t& r1, uint32_t& r2, uint32_t& r3,
                                            uint32_t addr) {
    asm volatile("ldmatrix.sync.aligned.m8n8.x4.shared.b16 {%0,%1,%2,%3}, [%4];"
                 : "=r"(r0), "=r"(r1), "=r"(r2), "=r"(r3) : "r"(addr));
}
__device__ __forceinline__ void mma_bf16(float* d, const uint32_t* a, const uint32_t* b) {
    asm volatile("mma.sync.aligned.m16n8k16.row.col.f32.bf16.bf16.f32 "
                 "{%0,%1,%2,%3}, {%4,%5,%6,%7}, {%8,%9}, {%0,%1,%2,%3};"
                 : "+f"(d[0]), "+f"(d[1]), "+f"(d[2]), "+f"(d[3])
                 : "r"(a[0]), "r"(a[1]), "r"(a[2]), "r"(a[3]), "r"(b[0]), "r"(b[1]));
}
__device__ __forceinline__ void lds128(float* v, uint32_t addr) {
    asm volatile("ld.shared.v4.f32 {%0,%1,%2,%3}, [%4];"
                 : "=f"(v[0]), "=f"(v[1]), "=f"(v[2]), "=f"(v[3]) : "r"(addr));
}
__device__ __forceinline__ void split3(float x, __nv_bfloat16* o, int stride) {
    __nv_bfloat16 hi = __float2bfloat16(x);
    __nv_bfloat16 lo = __float2bfloat16(x - __bfloat162float(hi));
    o[0] = hi; o[stride] = lo; o[2 * stride] = hi;
}
// proportional interleave: spread ng gemm blocks uniformly over total
__device__ __forceinline__ bool work_map(int bid, int ng, int total, int& widx) {
    long long p0 = ((long long)bid * ng) / total;
    long long p1 = ((long long)(bid + 1) * ng) / total;
    if (p1 > p0) { widx = (int)p0; return true; }
    widx = bid - (int)p0; return false;
}

// =====================================================================
// Attention body (R10-proven): per-warp online softmax, 2-deep cp.async
// staging. Smem: [tile0 16KB][tile1 16KB][AttnSmem]
// MODE 0: attn_q (write QC bf16). MODE 1: attn_g (c_, alpha, XCP bf16).
// =====================================================================
struct AttnSmem {
    float m[8]; float s[8]; float w8[8];
    float Mg, Sg;
    float sc[Tn];
    float acc[8][512];
};
#define ATTN_TILE_BYTES 16384
#define ATTN_SM_OFF (2 * ATTN_TILE_BYTES)

template<int MODE>
__device__ __forceinline__ void attn_body(
    char* smem_raw,
    const float* __restrict__ hist, size_t tstride, size_t row_off,
    const float* __restrict__ wvec,
    float* __restrict__ c_out,
    float* __restrict__ alpha_out,
    __nv_bfloat16* __restrict__ bf_out,
    int bf_stride)
{
    uint32_t sb = smem_u32(smem_raw);
    AttnSmem* sm = reinterpret_cast<AttnSmem*>(smem_raw + ATTN_SM_OFF);
    int tid = threadIdx.x;
    int lane = tid & 31;
    int w = tid >> 5;

    const float* src = hist + row_off;

    int trow_[4], c16_[4];
    #pragma unroll
    for (int i = 0; i < 4; i++) {
        int u = tid + 256 * i;
        trow_[i] = u >> 7;
        c16_[i] = u & 127;
    }

    float q[16];
    #pragma unroll
    for (int j = 0; j < 4; j++) {
        float4 t4 = *(const float4*)(wvec + lane * 4 + j * 128);
        q[j*4+0] = t4.x; q[j*4+1] = t4.y; q[j*4+2] = t4.z; q[j*4+3] = t4.w;
    }

    float m = -INFINITY, s = 0.0f;
    float acc[16];
    #pragma unroll
    for (int k = 0; k < 16; k++) acc[k] = 0.0f;

    // prologue: chunks 0, 1
    #pragma unroll
    for (int c = 0; c < 2; c++) {
        uint32_t dst = sb + (uint32_t)c * ATTN_TILE_BYTES;
        #pragma unroll
        for (int i = 0; i < 4; i++) {
            cp_async16(dst + (uint32_t)(trow_[i] * 2048 + c16_[i] * 16),
                       src + (size_t)(c * 8 + trow_[i]) * tstride + c16_[i] * 4);
        }
        cp_commit();
    }

    for (int i = 0; i < 25; i++) {
        if (i == 24) cp_wait<0>(); else cp_wait<1>();
        __syncthreads();

        uint32_t vbase = sb + (uint32_t)(i & 1) * ATTN_TILE_BYTES + (uint32_t)(w * 2048 + lane * 16);
        float v[16];
        #pragma unroll
        for (int j = 0; j < 4; j++) lds128(v + j * 4, vbase + j * 512);

        int t = i * 8 + w;
        float dot = 0.0f;
        #pragma unroll
        for (int k = 0; k < 16; k++) dot = fmaf(v[k], q[k], dot);
        #pragma unroll
        for (int o = 16; o > 0; o >>= 1) dot += __shfl_xor_sync(0xffffffffu, dot, o);

        if (MODE == 1 && lane == 0) sm->sc[t] = dot;

        float nm = fmaxf(m, dot);
        float rs = __expf(m - nm);
        float cf = __expf(dot - nm);
        #pragma unroll
        for (int k = 0; k < 16; k++) acc[k] = fmaf(acc[k], rs, cf * v[k]);
        s = fmaf(s, rs, cf);
        m = nm;

        __syncthreads();
        if (i + 2 < 25) {
            uint32_t dst = sb + (uint32_t)(i & 1) * ATTN_TILE_BYTES;
            #pragma unroll
            for (int j = 0; j < 4; j++) {
                cp_async16(dst + (uint32_t)(trow_[j] * 2048 + c16_[j] * 16),
                           src + (size_t)((i + 2) * 8 + trow_[j]) * tstride + c16_[j] * 4);
            }
            cp_commit();
        }
    }

    if (lane == 0) { sm->m[w] = m; sm->s[w] = s; }
    #pragma unroll
    for (int j = 0; j < 4; j++)
        #pragma unroll
        for (int u = 0; u < 4; u++)
            sm->acc[w][lane * 4 + j * 128 + u] = acc[j*4+u];
    __syncthreads();

    if (tid == 0) {
        float M = -INFINITY;
        #pragma unroll
        for (int k = 0; k < 8; k++) M = fmaxf(M, sm->m[k]);
        float S = 0.0f;
        #pragma unroll
        for (int k = 0; k < 8; k++) S += sm->s[k] * __expf(sm->m[k] - M);
        float invS = 1.0f / S;
        #pragma unroll
        for (int k = 0; k < 8; k++) sm->w8[k] = __expf(sm->m[k] - M) * invS;
        sm->Mg = M; sm->Sg = S;
    }
    __syncthreads();

    int c = tid * 2;
    float o0 = 0.0f, o1 = 0.0f;
    #pragma unroll
    for (int k = 0; k < 8; k++) {
        float wk = sm->w8[k];
        o0 = fmaf(sm->acc[k][c], wk, o0);
        o1 = fmaf(sm->acc[k][c + 1], wk, o1);
    }
    if (MODE == 1) {
        *(float2*)(c_out + c) = make_float2(o0, o1);
        split3(o0, bf_out + c,     bf_stride);
        split3(o1, bf_out + c + 1, bf_stride);
        if (tid < Tn) {
            float inv = 1.0f / sm->Sg;
            alpha_out[tid] = __expf(sm->sc[tid] - sm->Mg) * inv;
        }
    } else {
        split3(o0, bf_out + c,     bf_stride);
        split3(o1, bf_out + c + 1, bf_stride);
    }
}

// =====================================================================
// bf16 mma.sync GEMM body (R7-proven)
// =====================================================================
#define MAXT 5
struct TDesc {
    const __nv_bfloat16* A; const __nv_bfloat16* W;
    const float* bias; float* C;
    int K3; int M; int gridX; int start;
};
struct TBatch { TDesc d[MAXT]; int nd; };

#define DYN_SMEM_BYTES 65536

__device__ __forceinline__ void mma_gemm_body(const TBatch& tb, char* smem_raw, int bid)
{
    int tid = threadIdx.x;
    int wid = tid >> 5;
    int lane = tid & 31;

    int di = 0;
    #pragma unroll
    for (int k = 1; k < MAXT; k++)
        if (k < tb.nd && bid >= tb.d[k].start) di = k;
    const TDesc dd = tb.d[di];
    int local = bid - dd.start;
    int m0 = (local % dd.gridX) * 128;
    int n0 = (local / dd.gridX) * 128;
    const int K3 = dd.K3;
    const int nc = K3 >> 6;

    uint32_t sb = smem_u32(smem_raw);

    int lrow[4], lc16[4]; uint32_t swoff[4];
    #pragma unroll
    for (int i = 0; i < 4; i++) {
        int u = tid + 256 * i;
        int r = u >> 3, c16 = u & 7;
        lrow[i] = r; lc16[i] = c16;
        swoff[i] = (uint32_t)(r * 128 + 16 * (c16 ^ (r & 7)));
    }
    const __nv_bfloat16* Ab = dd.A + (size_t)n0 * K3;
    const __nv_bfloat16* Wb = dd.W + (size_t)m0 * K3;

    int xr = lane & 7;
    int lA_row = (lane & 7) + ((lane >> 3) & 1) * 8;
    int lA_kh = lane >> 4;
    int lB_row = (lane & 7) + (lane >> 4) * 8;
    int lB_kh = (lane >> 3) & 1;
    int wr = wid & 1;
    int wc = wid >> 1;
    uint32_t rbA[4], rbB[2];
    #pragma unroll
    for (int mt = 0; mt < 4; mt++) rbA[mt] = (uint32_t)((wr * 64 + mt * 16 + lA_row) * 128);
    #pragma unroll
    for (int p = 0; p < 2; p++) rbB[p] = (uint32_t)((wc * 32 + p * 16 + lB_row) * 128);

    float acc[4][4][4];
    #pragma unroll
    for (int mt = 0; mt < 4; mt++)
        #pragma unroll
        for (int nt = 0; nt < 4; nt++)
            #pragma unroll
            for (int r = 0; r < 4; r++) acc[mt][nt][r] = 0.0f;

    {
        uint32_t ba = sb, bb = sb + 16384u;
        #pragma unroll
        for (int i = 0; i < 4; i++) {
            cp_async16(ba + swoff[i], Ab + (size_t)lrow[i] * K3 + lc16[i] * 8);
            cp_async16(bb + swoff[i], Wb + (size_t)lrow[i] * K3 + lc16[i] * 8);
        }
        cp_commit();
    }

    for (int c = 0; c < nc; c++) {
        if (c + 1 < nc) {
            uint32_t ba = sb + (uint32_t)((c + 1) & 1) * 32768u;
            uint32_t bb = ba + 16384u;
            int koff = (c + 1) * 64;
            #pragma unroll
            for (int i = 0; i < 4; i++) {
                cp_async16(ba + swoff[i], Ab + (size_t)lrow[i] * K3 + koff + lc16[i] * 8);
                cp_async16(bb + swoff[i], Wb + (size_t)lrow[i] * K3 + koff + lc16[i] * 8);
            }
            cp_commit();
            cp_wait<1>();
        } else {
            cp_wait<0>();
        }
        __syncthreads();

        uint32_t ba = sb + (uint32_t)(c & 1) * 32768u;
        uint32_t bb = ba + 16384u;
        #pragma unroll
        for (int s = 0; s < 4; s++) {
            uint32_t a[4][4];
            #pragma unroll
            for (int mt = 0; mt < 4; mt++) {
                uint32_t addr = ba + rbA[mt] + 16u * (uint32_t)(((s << 1) + lA_kh) ^ xr);
                ldmatrix_x4(a[mt][0], a[mt][1], a[mt][2], a[mt][3], addr);
            }
            uint32_t bfr[4][2];
            #pragma unroll
            for (int p = 0; p < 2; p++) {
                uint32_t addr = bb + rbB[p] + 16u * (uint32_t)(((s << 1) + lB_kh) ^ xr);
                ldmatrix_x4(bfr[2*p][0], bfr[2*p][1], bfr[2*p+1][0], bfr[2*p+1][1], addr);
            }
            #pragma unroll
            for (int mt = 0; mt < 4; mt++)
                #pragma unroll
                for (int nt = 0; nt < 4; nt++)
                    mma_bf16(acc[mt][nt], a[mt], bfr[nt]);
        }
        __syncthreads();
    }

    int g = lane >> 2;
    int t2 = (lane & 3) * 2;
    #pragma unroll
    for (int mt = 0; mt < 4; mt++) {
        int row0 = n0 + wr * 64 + mt * 16 + g;
        #pragma unroll
        for (int nt = 0; nt < 4; nt++) {
            int col = m0 + wc * 32 + nt * 8 + t2;
            float b0 = 0.0f, b1 = 0.0f;
            if (dd.bias) { b0 = dd.bias[col]; b1 = dd.bias[col + 1]; }
            float2 v0 = make_float2(acc[mt][nt][0] + b0, acc[mt][nt][1] + b1);
            float2 v1 = make_float2(acc[mt][nt][2] + b0, acc[mt][nt][3] + b1);
            *(float2*)(dd.C + (size_t)row0 * dd.M + col) = v0;
            *(float2*)(dd.C + (size_t)(row0 + 8) * dd.M + col) = v1;
        }
    }
}

// =====================================================================
// Fused launch with interleaved work map:
// gemm blocks spread uniformly; others: [0,nag) attn_g | rest attn_q
// =====================================================================
__global__ __launch_bounds__(256, 2) void fused_all(
    TBatch tb, int n_gemm, int n_attn_g,
    const float* __restrict__ g_hist, const float* __restrict__ w_att,
    float* __restrict__ c_out, float* __restrict__ alpha_base,
    __nv_bfloat16* __restrict__ xcp_bf,
    const float* __restrict__ q_hist, const float* __restrict__ xt,
    __nv_bfloat16* __restrict__ qc_bf)
{
    extern __shared__ __align__(128) char smem_raw[];
    int widx;
    if (work_map(blockIdx.x, n_gemm, gridDim.x, widx)) {
        mma_gemm_body(tb, smem_raw, widx);
    } else if (widx < n_attn_g) {
        int b = widx;
        attn_body<1>(smem_raw, g_hist, (size_t)Bn * D_G, (size_t)b * D_G,
                     w_att,
                     c_out + (size_t)b * D_G,
                     alpha_base + (size_t)b * Tn,
                     xcp_bf + (size_t)b * 4608 + 1024, 1536);
    } else {
        int n = widx - n_attn_g;
        attn_body<0>(smem_raw, q_hist, (size_t)Bn * PARTY * D_P, (size_t)n * D_P,
                     xt + (size_t)n * D_P,
                     nullptr, nullptr,
                     qc_bf + (size_t)n * 1536, 512);
    }
}

// =====================================================================
// conversions (batched): fp32 -> bf16 hi/lo split, with gather modes.
// mode 0: activation [hi|lo|hi]  mode 1: weight [hi|hi|lo]
// mode 2: XCG gather [U | q0_sel]  mode 3: E0SW party-swap gather of e0
// =====================================================================
#define MAXC 13
struct CDesc { const float* in; __nv_bfloat16* out; int Kin; int Kout; int colofs; int total; int start; int mode; };
struct CBatch { CDesc d[MAXC]; int nd; };

__global__ __launch_bounds__(256) void conv_batch(CBatch cb,
    const float* __restrict__ U, const float* __restrict__ qmask,
    const float* __restrict__ q0, const float* __restrict__ e0)
{
    int bid = blockIdx.x;
    int di = 0;
    #pragma unroll
    for (int k = 1; k < MAXC; k++)
        if (k < cb.nd && bid >= cb.d[k].start) di = k;
    const CDesc dd = cb.d[di];
    int base = (bid - dd.start) * 2048 + threadIdx.x;
    #pragma unroll
    for (int i = 0; i < 8; i++) {
        int idx = base + i * 256;
        if (idx >= dd.total) break;
        int r = idx / dd.Kin;
        int k = idx - r * dd.Kin;
        float x;
        if (dd.mode == 2) {
            if (k < D_M) x = U[(size_t)r * D_M + k];
            else {
                int qi = (qmask[r * 2 + 1] > qmask[r * 2 + 0]) ? 1 : 0;
                x = q0[(size_t)(r * 2 + qi) * D_P + (k - D_M)];
            }
        } else if (dd.mode == 3) {
            int b = r >> 1, p = r & 1;
            x = e0[(size_t)(b * 2 + (1 - p)) * D_E + k];
        } else {
            x = dd.in[idx];
        }
        __nv_bfloat16 hi = __float2bfloat16(x);
        __nv_bfloat16 lo = __float2bfloat16(x - __bfloat162float(hi));
        __nv_bfloat16* o = dd.out + (size_t)r * 3 * dd.Kout + dd.colofs + k;
        if (dd.mode == 1) { o[0] = hi; o[dd.Kout] = hi; o[2 * dd.Kout] = lo; }
        else              { o[0] = hi; o[dd.Kout] = lo; o[2 * dd.Kout] = hi; }
    }
}

// =====================================================================
// GRU epilogue (plain lightweight kernel — R10-proven)
// =====================================================================
__global__ void gru_epi(const float* __restrict__ gi, const float* __restrict__ gh,
                        const float* __restrict__ h, float* __restrict__ out,
                        int N, int D, int mode, const float* __restrict__ qmask)
{
    int idx = blockIdx.x * blockDim.x + threadIdx.x;
    if (idx >= N * D) return;
    int n = idx / D;
    int j = idx - n * D;
    int gn = (mode == 1) ? (n >> 1) : n;
    size_t gib = (size_t)gn * 3 * D + j;
    size_t ghb = (size_t)n * 3 * D + j;
    float ir = gi[gib],          hr = gh[ghb];
    float iz = gi[gib + D],      hz = gh[ghb + D];
    float in_ = gi[gib + 2 * D], hn = gh[ghb + 2 * D];
    float r = 1.0f / (1.0f + __expf(-(ir + hr)));
    float z = 1.0f / (1.0f + __expf(-(iz + hz)));
    float nn = tanhf(in_ + r * hn);
    float hv = h[idx];
    float val = (1.0f - z) * nn + z * hv;
    if (mode == 1) {
        float qm = qmask[n];
        val = hv * (1.0f - qm) + val * qm;
    }
    out[idx] = val;
}

// =====================================================================
// launch
// =====================================================================
extern "C" void kernel_launch(void* const* d_in, const int* in_sizes, int n_in,
                              void* d_out, int out_size)
{
    const float* U       = (const float*)d_in[0];
    const float* qmask   = (const float*)d_in[1];
    const float* g_hist  = (const float*)d_in[2];
    const float* q0      = (const float*)d_in[3];
    const float* q_hist  = (const float*)d_in[4];
    const float* e0      = (const float*)d_in[5];
    const float* w_ih_g  = (const float*)d_in[6];
    const float* w_hh_g  = (const float*)d_in[7];
    const float* b_ih_g  = (const float*)d_in[8];
    const float* b_hh_g  = (const float*)d_in[9];
    const float* w_ih_p  = (const float*)d_in[10];
    const float* w_hh_p  = (const float*)d_in[11];
    const float* b_ih_p  = (const float*)d_in[12];
    const float* b_hh_p  = (const float*)d_in[13];
    const float* w_ih_e  = (const float*)d_in[14];
    const float* w_hh_e  = (const float*)d_in[15];
    const float* b_ih_e  = (const float*)d_in[16];
    const float* b_hh_e  = (const float*)d_in[17];
    const float* w_att   = (const float*)d_in[18];
    const float* w_trans = (const float*)d_in[19];
    float* out = (float*)d_out;

    static int smem_set = 0;
    if (!smem_set) {
        cudaFuncSetAttribute(fused_all, cudaFuncAttributeMaxDynamicSharedMemorySize, DYN_SMEM_BYTES);
        smem_set = 1;
    }

    float *gi_p, *gh_p, *ghe_p, *ghp_p, *xt_p, *gih_p;
    __nv_bfloat16* bf;
    cudaGetSymbolAddress((void**)&gi_p,   d_gi_buf);
    cudaGetSymbolAddress((void**)&gh_p,   d_gh_buf);
    cudaGetSymbolAddress((void**)&ghe_p,  d_ghe_buf);
    cudaGetSymbolAddress((void**)&ghp_p,  d_ghp_buf);
    cudaGetSymbolAddress((void**)&xt_p,   d_xt_buf);
    cudaGetSymbolAddress((void**)&gih_p,  d_gih_buf);
    cudaGetSymbolAddress((void**)&bf,     d_bf);

    const float* g_last = g_hist + (size_t)(Tn - 1) * Bn * D_G;

    // ---- L0: single conv launch (weights + activations + gathers) ----
    {
        CBatch cb; cb.nd = 13;
        int s = 0;
        auto add = [&](int i, const float* in, unsigned long long off,
                       int Kin, int Kout, int colofs, int total, int mode) {
            cb.d[i] = { in, bf + off, Kin, Kout, colofs, total, s, mode };
            s += (total + 2047) / 2048;
        };
        add(0,  w_ih_g,  OFF_WIHG,  1536, 1536, 0, 1536 * 1536, 1);
        add(1,  w_hh_g,  OFF_WHHG,  512,  512,  0, 1536 * 512,  1);
        add(2,  w_ih_p,  OFF_WIHP,  1536, 1536, 0, 1536 * 1536, 1);
        add(3,  w_hh_p,  OFF_WHHP,  512,  512,  0, 1536 * 512,  1);
        add(4,  w_ih_e,  OFF_WIHE,  512,  512,  0, 1536 * 512,  1);
        add(5,  w_hh_e,  OFF_WHHE,  512,  512,  0, 1536 * 512,  1);
        add(6,  w_trans, OFF_WTR,   512,  512,  0, 512 * 512,   1);
        add(7,  nullptr, OFF_XCG,   1536, 1536, 0, 512 * 1536,  2);   // [U|q0_sel] gather
        add(8,  g_last,  OFF_GLAST, 512,  512,  0, 512 * 512,   0);
        add(9,  q0,      OFF_Q0,    512,  512,  0, 1024 * 512,  0);
        add(10, nullptr, OFF_E0SW,  512,  512,  0, 1024 * 512,  3);   // e0 party-swap gather
        add(11, e0,      OFF_E0,    512,  512,  0, 1024 * 512,  0);
        add(12, U,       OFF_XCP,   1024, 1536, 0, 512 * 1024,  0);   // XCP U-columns
        conv_batch<<<s, 256>>>(cb, U, qmask, q0, e0);
    }

    // ---- L1: fused {gi_g, gh_g, gh_p, xt, gh_e} + attn_g (INTERLEAVED) ----
    {
        TBatch tb; tb.nd = 5;
        int s = 0;
        tb.d[0] = { bf + OFF_XCG,   bf + OFF_WIHG, b_ih_g, gi_p,  4608, 3 * D_G, 12, s }; s += 48;
        tb.d[1] = { bf + OFF_GLAST, bf + OFF_WHHG, b_hh_g, gh_p,  1536, 3 * D_G, 12, s }; s += 48;
        tb.d[2] = { bf + OFF_Q0,    bf + OFF_WHHP, b_hh_p, ghp_p, 1536, 3 * D_P, 12, s }; s += 96;
        tb.d[3] = { bf + OFF_E0SW,  bf + OFF_WTR,  nullptr, xt_p, 1536, D_P,      4, s }; s += 32;
        tb.d[4] = { bf + OFF_E0,    bf + OFF_WHHE, b_hh_e, ghe_p, 1536, 3 * D_E, 12, s }; s += 96;
        int total = s + Bn;
        fused_all<<<total, 256, DYN_SMEM_BYTES>>>(tb, s, Bn, g_hist, w_att,
                                                  out + C_OFF, out + A_OFF, bf + OFF_XCP,
                                                  q_hist, xt_p, bf + OFF_QC);
    }

    // ---- L2: fused {gi_p} + attn_q (INTERLEAVED) ----
    {
        TBatch tb; tb.nd = 1;
        tb.d[0] = { bf + OFF_XCP, bf + OFF_WIHP, b_ih_p, gih_p, 4608, 3 * D_P, 12, 0 };
        int s = 48;
        int total = s + Bn * PARTY;
        fused_all<<<total, 256, DYN_SMEM_BYTES>>>(tb, s, 0, g_hist, w_att,
                                                  nullptr, nullptr, nullptr,
                                                  q_hist, xt_p, bf + OFF_QC);
    }

    // ---- L3: epilogues g, p (plain kernels) ----
    gru_epi<<<(Bn * D_G + 255) / 256, 256>>>(gi_p, gh_p, g_last, out + G_OFF, Bn, D_G, 0, nullptr);
    gru_epi<<<(Bn * PARTY * D_P + 255) / 256, 256>>>(gih_p, ghp_p, q0, out + Q_OFF,
                                                     Bn * PARTY, D_P, 1, qmask);

    // ---- L4: gi_e (needs QC) ----
    {
        TBatch tb; tb.nd = 1;
        tb.d[0] = { bf + OFF_QC, bf + OFF_WIHE, b_ih_e, gi_p, 1536, 3 * D_E, 12, 0 };
        fused_all<<<96, 256, DYN_SMEM_BYTES>>>(tb, 96, 0, g_hist, w_att,
                                               nullptr, nullptr, nullptr,
                                               q_hist, xt_p, bf + OFF_QC);
    }

    // ---- L5: epilogue e ----
    gru_epi<<<(Bn * PARTY * D_E + 255) / 256, 256>>>(gi_p, ghe_p, e0, out + E_OFF,
                                                     Bn * PARTY, D_E, 0, nullptr);
}

// round 14
// speedup vs baseline: 1.3548x; 1.2356x over previous
#include <cuda_runtime.h>
#include <cuda_bf16.h>
#include <math.h>
#include <stdint.h>

#define Bn 512
#define Tn 200
#define PARTY 2
#define D_M 1024
#define D_G 512
#define D_P 512
#define D_E 512

// Output layout (flattened tuple): g_, q_, e_, c_, alpha_out
#define G_OFF 0
#define Q_OFF (Bn * D_G)
#define E_OFF (Q_OFF + Bn * PARTY * D_P)
#define C_OFF (E_OFF + Bn * PARTY * D_E)
#define A_OFF (C_OFF + Bn * D_G)

// ---------------- fp32 scratch ----------------
__device__ float d_gi_buf[(Bn * PARTY) * 3 * D_G];    // gi_g ; later gi_e
__device__ float d_gh_buf[Bn * 3 * D_G];              // gh_g
__device__ float d_ghe_buf[(Bn * PARTY) * 3 * D_E];   // gh_e
__device__ float d_ghp_buf[(Bn * PARTY) * 3 * D_P];   // gh_p
__device__ float d_xt_buf[Bn * PARTY * D_P];
__device__ float d_gih_buf[Bn * 3 * D_P];             // gi_p dedup

// ---------------- bf16 split scratch (hi/lo concat, K tripled) ----------------
#define OFF_WIHG  0ull                       // 1536 x 4608
#define OFF_WHHG  (OFF_WIHG  + 7077888ull)   // 1536 x 1536
#define OFF_WIHP  (OFF_WHHG  + 2359296ull)   // 1536 x 4608
#define OFF_WHHP  (OFF_WIHP  + 7077888ull)   // 1536 x 1536
#define OFF_WIHE  (OFF_WHHP  + 2359296ull)   // 1536 x 1536
#define OFF_WHHE  (OFF_WIHE  + 2359296ull)   // 1536 x 1536
#define OFF_WTR   (OFF_WHHE  + 2359296ull)   // 512 x 1536
#define OFF_XCG   (OFF_WTR   + 786432ull)    // 512 x 4608 (gather-conv from U/qmask/q0)
#define OFF_GLAST (OFF_XCG   + 2359296ull)   // 512 x 1536
#define OFF_Q0    (OFF_GLAST + 786432ull)    // 1024 x 1536
#define OFF_E0SW  (OFF_Q0    + 1572864ull)   // 1024 x 1536 (gather-conv from e0)
#define OFF_E0    (OFF_E0SW  + 1572864ull)   // 1024 x 1536
#define OFF_XCP   (OFF_E0    + 1572864ull)   // 512 x 4608 (U-cols by conv; c_-cols by attn_g)
#define OFF_QC    (OFF_XCP   + 2359296ull)   // 1024 x 1536 (by attn_q)
#define BF_TOTAL  (OFF_QC    + 1572864ull)
__device__ __align__(16) __nv_bfloat16 d_bf[BF_TOTAL];

// =====================================================================
// helpers
// =====================================================================
__device__ __forceinline__ uint32_t smem_u32(const void* p) {
    uint32_t r;
    asm("{ .reg .u64 t; cvta.to.shared.u64 t, %1; cvt.u32.u64 %0, t; }" : "=r"(r) : "l"(p));
    return r;
}
__device__ __forceinline__ void cp_async16(uint32_t dst, const void* src) {
    asm volatile("cp.async.cg.shared.global [%0], [%1], 16;" :: "r"(dst), "l"(src) : "memory");
}
__device__ __forceinline__ void cp_commit() {
    asm volatile("cp.async.commit_group;" ::: "memory");
}
template<int N>
__device__ __forceinline__ void cp_wait() {
    asm volatile("cp.async.wait_group %0;" :: "n"(N) : "memory");
}
__device__ __forceinline__ void ldmatrix_x4(uint32_t& r0, uint32_t& r1, uint32_t& r2, uint32_t& r3,
                                            uint32_t addr) {
    asm volatile("ldmatrix.sync.aligned.m8n8.x4.shared.b16 {%0,%1,%2,%3}, [%4];"
                 : "=r"(r0), "=r"(r1), "=r"(r2), "=r"(r3) : "r"(addr));
}
__device__ __forceinline__ void mma_bf16(float* d, const uint32_t* a, const uint32_t* b) {
    asm volatile("mma.sync.aligned.m16n8k16.row.col.f32.bf16.bf16.f32 "
                 "{%0,%1,%2,%3}, {%4,%5,%6,%7}, {%8,%9}, {%0,%1,%2,%3};"
                 : "+f"(d[0]), "+f"(d[1]), "+f"(d[2]), "+f"(d[3])
                 : "r"(a[0]), "r"(a[1]), "r"(a[2]), "r"(a[3]), "r"(b[0]), "r"(b[1]));
}
__device__ __forceinline__ void lds128(float* v, uint32_t addr) {
    asm volatile("ld.shared.v4.f32 {%0,%1,%2,%3}, [%4];"
                 : "=f"(v[0]), "=f"(v[1]), "=f"(v[2]), "=f"(v[3]) : "r"(addr));
}
__device__ __forceinline__ void split3(float x, __nv_bfloat16* o, int stride) {
    __nv_bfloat16 hi = __float2bfloat16(x);
    __nv_bfloat16 lo = __float2bfloat16(x - __bfloat162float(hi));
    o[0] = hi; o[stride] = lo; o[2 * stride] = hi;
}

// =====================================================================
// Attention body: per-warp online softmax with PER-WARP cp.async staging.
// Warp w owns an 8KB smem region (4 row-buffers of 2KB) and stages its own
// timesteps t = w + 8i, 4 deep. Lane l loads exactly the 16B units it later
// reads (unit l+32k <-> read offset l*16 + k*512), so wait_group alone gives
// visibility — NO block/warp syncs in the main loop.
// MODE 0: attn_q (write QC bf16). MODE 1: attn_g (c_, alpha, XCP bf16).
// =====================================================================
struct AttnSmem {
    float m[8]; float s[8]; float w8[8];
    float Mg, Sg;
    float sc[Tn];
    float acc[8][512];
};
#define ATTN_WARP_BYTES 8192
#define ATTN_SM_OFF 65536
#define DYN_SMEM_BYTES (65536 + 17408)

template<int MODE>
__device__ __forceinline__ void attn_body(
    char* smem_raw,
    const float* __restrict__ hist, size_t tstride, size_t row_off,
    const float* __restrict__ wvec,
    float* __restrict__ c_out,
    float* __restrict__ alpha_out,
    __nv_bfloat16* __restrict__ bf_out,
    int bf_stride)
{
    uint32_t sb = smem_u32(smem_raw);
    AttnSmem* sm = reinterpret_cast<AttnSmem*>(smem_raw + ATTN_SM_OFF);
    int tid = threadIdx.x;
    int lane = tid & 31;
    int w = tid >> 5;

    const float* src = hist + row_off;
    uint32_t wb = sb + (uint32_t)w * ATTN_WARP_BYTES;

    float q[16];
    #pragma unroll
    for (int j = 0; j < 4; j++) {
        float4 t4 = *(const float4*)(wvec + lane * 4 + j * 128);
        q[j*4+0] = t4.x; q[j*4+1] = t4.y; q[j*4+2] = t4.z; q[j*4+3] = t4.w;
    }

    float m = -INFINITY, s = 0.0f;
    float acc[16];
    #pragma unroll
    for (int k = 0; k < 16; k++) acc[k] = 0.0f;

    // prologue: stage rows i=0..3 (t = i*8 + w), one commit group per row
    #pragma unroll
    for (int p = 0; p < 4; p++) {
        uint32_t dst = wb + (uint32_t)p * 2048u;
        const float* rp = src + (size_t)(p * 8 + w) * tstride;
        #pragma unroll
        for (int k = 0; k < 4; k++)
            cp_async16(dst + (uint32_t)((lane + 32 * k) * 16), rp + (lane + 32 * k) * 4);
        cp_commit();
    }

    for (int i = 0; i < 25; i++) {
        if (i <= 21)      cp_wait<3>();
        else if (i == 22) cp_wait<2>();
        else if (i == 23) cp_wait<1>();
        else              cp_wait<0>();

        uint32_t vbase = wb + (uint32_t)(i & 3) * 2048u + (uint32_t)(lane * 16);
        float v[16];
        #pragma unroll
        for (int j = 0; j < 4; j++) lds128(v + j * 4, vbase + j * 512);

        int t = i * 8 + w;
        float dot = 0.0f;
        #pragma unroll
        for (int k = 0; k < 16; k++) dot = fmaf(v[k], q[k], dot);
        #pragma unroll
        for (int o = 16; o > 0; o >>= 1) dot += __shfl_xor_sync(0xffffffffu, dot, o);

        if (MODE == 1 && lane == 0) sm->sc[t] = dot;

        float nm = fmaxf(m, dot);
        float rs = __expf(m - nm);
        float cf = __expf(dot - nm);
        #pragma unroll
        for (int k = 0; k < 16; k++) acc[k] = fmaf(acc[k], rs, cf * v[k]);
        s = fmaf(s, rs, cf);
        m = nm;

        if (i + 4 < 25) {
            uint32_t dst = wb + (uint32_t)(i & 3) * 2048u;
            const float* rp = src + (size_t)((i + 4) * 8 + w) * tstride;
            #pragma unroll
            for (int k = 0; k < 4; k++)
                cp_async16(dst + (uint32_t)((lane + 32 * k) * 16), rp + (lane + 32 * k) * 4);
            cp_commit();
        }
    }

    if (lane == 0) { sm->m[w] = m; sm->s[w] = s; }
    #pragma unroll
    for (int j = 0; j < 4; j++)
        #pragma unroll
        for (int u = 0; u < 4; u++)
            sm->acc[w][lane * 4 + j * 128 + u] = acc[j*4+u];
    __syncthreads();

    if (tid == 0) {
        float M = -INFINITY;
        #pragma unroll
        for (int k = 0; k < 8; k++) M = fmaxf(M, sm->m[k]);
        float S = 0.0f;
        #pragma unroll
        for (int k = 0; k < 8; k++) S += sm->s[k] * __expf(sm->m[k] - M);
        float invS = 1.0f / S;
        #pragma unroll
        for (int k = 0; k < 8; k++) sm->w8[k] = __expf(sm->m[k] - M) * invS;
        sm->Mg = M; sm->Sg = S;
    }
    __syncthreads();

    int c = tid * 2;
    float o0 = 0.0f, o1 = 0.0f;
    #pragma unroll
    for (int k = 0; k < 8; k++) {
        float wk = sm->w8[k];
        o0 = fmaf(sm->acc[k][c], wk, o0);
        o1 = fmaf(sm->acc[k][c + 1], wk, o1);
    }
    if (MODE == 1) {
        *(float2*)(c_out + c) = make_float2(o0, o1);
        split3(o0, bf_out + c,     bf_stride);
        split3(o1, bf_out + c + 1, bf_stride);
        if (tid < Tn) {
            float inv = 1.0f / sm->Sg;
            alpha_out[tid] = __expf(sm->sc[tid] - sm->Mg) * inv;
        }
    } else {
        split3(o0, bf_out + c,     bf_stride);
        split3(o1, bf_out + c + 1, bf_stride);
    }
}

// =====================================================================
// bf16 mma.sync GEMM body (R7-proven)
// =====================================================================
#define MAXT 5
struct TDesc {
    const __nv_bfloat16* A; const __nv_bfloat16* W;
    const float* bias; float* C;
    int K3; int M; int gridX; int start;
};
struct TBatch { TDesc d[MAXT]; int nd; };

__device__ __forceinline__ void mma_gemm_body(const TBatch& tb, char* smem_raw, int bid)
{
    int tid = threadIdx.x;
    int wid = tid >> 5;
    int lane = tid & 31;

    int di = 0;
    #pragma unroll
    for (int k = 1; k < MAXT; k++)
        if (k < tb.nd && bid >= tb.d[k].start) di = k;
    const TDesc dd = tb.d[di];
    int local = bid - dd.start;
    int m0 = (local % dd.gridX) * 128;
    int n0 = (local / dd.gridX) * 128;
    const int K3 = dd.K3;
    const int nc = K3 >> 6;

    uint32_t sb = smem_u32(smem_raw);

    int lrow[4], lc16[4]; uint32_t swoff[4];
    #pragma unroll
    for (int i = 0; i < 4; i++) {
        int u = tid + 256 * i;
        int r = u >> 3, c16 = u & 7;
        lrow[i] = r; lc16[i] = c16;
        swoff[i] = (uint32_t)(r * 128 + 16 * (c16 ^ (r & 7)));
    }
    const __nv_bfloat16* Ab = dd.A + (size_t)n0 * K3;
    const __nv_bfloat16* Wb = dd.W + (size_t)m0 * K3;

    int xr = lane & 7;
    int lA_row = (lane & 7) + ((lane >> 3) & 1) * 8;
    int lA_kh = lane >> 4;
    int lB_row = (lane & 7) + (lane >> 4) * 8;
    int lB_kh = (lane >> 3) & 1;
    int wr = wid & 1;
    int wc = wid >> 1;
    uint32_t rbA[4], rbB[2];
    #pragma unroll
    for (int mt = 0; mt < 4; mt++) rbA[mt] = (uint32_t)((wr * 64 + mt * 16 + lA_row) * 128);
    #pragma unroll
    for (int p = 0; p < 2; p++) rbB[p] = (uint32_t)((wc * 32 + p * 16 + lB_row) * 128);

    float acc[4][4][4];
    #pragma unroll
    for (int mt = 0; mt < 4; mt++)
        #pragma unroll
        for (int nt = 0; nt < 4; nt++)
            #pragma unroll
            for (int r = 0; r < 4; r++) acc[mt][nt][r] = 0.0f;

    {
        uint32_t ba = sb, bb = sb + 16384u;
        #pragma unroll
        for (int i = 0; i < 4; i++) {
            cp_async16(ba + swoff[i], Ab + (size_t)lrow[i] * K3 + lc16[i] * 8);
            cp_async16(bb + swoff[i], Wb + (size_t)lrow[i] * K3 + lc16[i] * 8);
        }
        cp_commit();
    }

    for (int c = 0; c < nc; c++) {
        if (c + 1 < nc) {
            uint32_t ba = sb + (uint32_t)((c + 1) & 1) * 32768u;
            uint32_t bb = ba + 16384u;
            int koff = (c + 1) * 64;
            #pragma unroll
            for (int i = 0; i < 4; i++) {
                cp_async16(ba + swoff[i], Ab + (size_t)lrow[i] * K3 + koff + lc16[i] * 8);
                cp_async16(bb + swoff[i], Wb + (size_t)lrow[i] * K3 + koff + lc16[i] * 8);
            }
            cp_commit();
            cp_wait<1>();
        } else {
            cp_wait<0>();
        }
        __syncthreads();

        uint32_t ba = sb + (uint32_t)(c & 1) * 32768u;
        uint32_t bb = ba + 16384u;
        #pragma unroll
        for (int s = 0; s < 4; s++) {
            uint32_t a[4][4];
            #pragma unroll
            for (int mt = 0; mt < 4; mt++) {
                uint32_t addr = ba + rbA[mt] + 16u * (uint32_t)(((s << 1) + lA_kh) ^ xr);
                ldmatrix_x4(a[mt][0], a[mt][1], a[mt][2], a[mt][3], addr);
            }
            uint32_t bfr[4][2];
            #pragma unroll
            for (int p = 0; p < 2; p++) {
                uint32_t addr = bb + rbB[p] + 16u * (uint32_t)(((s << 1) + lB_kh) ^ xr);
                ldmatrix_x4(bfr[2*p][0], bfr[2*p][1], bfr[2*p+1][0], bfr[2*p+1][1], addr);
            }
            #pragma unroll
            for (int mt = 0; mt < 4; mt++)
                #pragma unroll
                for (int nt = 0; nt < 4; nt++)
                    mma_bf16(acc[mt][nt], a[mt], bfr[nt]);
        }
        __syncthreads();
    }

    int g = lane >> 2;
    int t2 = (lane & 3) * 2;
    #pragma unroll
    for (int mt = 0; mt < 4; mt++) {
        int row0 = n0 + wr * 64 + mt * 16 + g;
        #pragma unroll
        for (int nt = 0; nt < 4; nt++) {
            int col = m0 + wc * 32 + nt * 8 + t2;
            float b0 = 0.0f, b1 = 0.0f;
            if (dd.bias) { b0 = dd.bias[col]; b1 = dd.bias[col + 1]; }
            float2 v0 = make_float2(acc[mt][nt][0] + b0, acc[mt][nt][1] + b1);
            float2 v1 = make_float2(acc[mt][nt][2] + b0, acc[mt][nt][3] + b1);
            *(float2*)(dd.C + (size_t)row0 * dd.M + col) = v0;
            *(float2*)(dd.C + (size_t)(row0 + 8) * dd.M + col) = v1;
        }
    }
}

// =====================================================================
// Fused launch, ORDERED (gemm-first — condemned interleave removed):
// [0,ng) gemm | [ng, ng+nag) attn_g | rest attn_q
// =====================================================================
__global__ __launch_bounds__(256, 2) void fused_all(
    TBatch tb, int n_gemm, int n_attn_g,
    const float* __restrict__ g_hist, const float* __restrict__ w_att,
    float* __restrict__ c_out, float* __restrict__ alpha_base,
    __nv_bfloat16* __restrict__ xcp_bf,
    const float* __restrict__ q_hist, const float* __restrict__ xt,
    __nv_bfloat16* __restrict__ qc_bf)
{
    extern __shared__ __align__(128) char smem_raw[];
    int bid = blockIdx.x;
    if (bid < n_gemm) {
        mma_gemm_body(tb, smem_raw, bid);
    } else if (bid < n_gemm + n_attn_g) {
        int b = bid - n_gemm;
        attn_body<1>(smem_raw, g_hist, (size_t)Bn * D_G, (size_t)b * D_G,
                     w_att,
                     c_out + (size_t)b * D_G,
                     alpha_base + (size_t)b * Tn,
                     xcp_bf + (size_t)b * 4608 + 1024, 1536);
    } else {
        int n = bid - n_gemm - n_attn_g;
        attn_body<0>(smem_raw, q_hist, (size_t)Bn * PARTY * D_P, (size_t)n * D_P,
                     xt + (size_t)n * D_P,
                     nullptr, nullptr,
                     qc_bf + (size_t)n * 1536, 512);
    }
}

// =====================================================================
// conversions (batched): fp32 -> bf16 hi/lo split, with gather modes.
// mode 0: activation [hi|lo|hi]  mode 1: weight [hi|hi|lo]
// mode 2: XCG gather [U | q0_sel]  mode 3: E0SW party-swap gather of e0
// =====================================================================
#define MAXC 13
struct CDesc { const float* in; __nv_bfloat16* out; int Kin; int Kout; int colofs; int total; int start; int mode; };
struct CBatch { CDesc d[MAXC]; int nd; };

__global__ __launch_bounds__(256) void conv_batch(CBatch cb,
    const float* __restrict__ U, const float* __restrict__ qmask,
    const float* __restrict__ q0, const float* __restrict__ e0)
{
    int bid = blockIdx.x;
    int di = 0;
    #pragma unroll
    for (int k = 1; k < MAXC; k++)
        if (k < cb.nd && bid >= cb.d[k].start) di = k;
    const CDesc dd = cb.d[di];
    int base = (bid - dd.start) * 2048 + threadIdx.x;
    #pragma unroll
    for (int i = 0; i < 8; i++) {
        int idx = base + i * 256;
        if (idx >= dd.total) break;
        int r = idx / dd.Kin;
        int k = idx - r * dd.Kin;
        float x;
        if (dd.mode == 2) {
            if (k < D_M) x = U[(size_t)r * D_M + k];
            else {
                int qi = (qmask[r * 2 + 1] > qmask[r * 2 + 0]) ? 1 : 0;
                x = q0[(size_t)(r * 2 + qi) * D_P + (k - D_M)];
            }
        } else if (dd.mode == 3) {
            int b = r >> 1, p = r & 1;
            x = e0[(size_t)(b * 2 + (1 - p)) * D_E + k];
        } else {
            x = dd.in[idx];
        }
        __nv_bfloat16 hi = __float2bfloat16(x);
        __nv_bfloat16 lo = __float2bfloat16(x - __bfloat162float(hi));
        __nv_bfloat16* o = dd.out + (size_t)r * 3 * dd.Kout + dd.colofs + k;
        if (dd.mode == 1) { o[0] = hi; o[dd.Kout] = hi; o[2 * dd.Kout] = lo; }
        else              { o[0] = hi; o[dd.Kout] = lo; o[2 * dd.Kout] = hi; }
    }
}

// =====================================================================
// GRU epilogue (plain lightweight kernel — R10-proven)
// =====================================================================
__global__ void gru_epi(const float* __restrict__ gi, const float* __restrict__ gh,
                        const float* __restrict__ h, float* __restrict__ out,
                        int N, int D, int mode, const float* __restrict__ qmask)
{
    int idx = blockIdx.x * blockDim.x + threadIdx.x;
    if (idx >= N * D) return;
    int n = idx / D;
    int j = idx - n * D;
    int gn = (mode == 1) ? (n >> 1) : n;
    size_t gib = (size_t)gn * 3 * D + j;
    size_t ghb = (size_t)n * 3 * D + j;
    float ir = gi[gib],          hr = gh[ghb];
    float iz = gi[gib + D],      hz = gh[ghb + D];
    float in_ = gi[gib + 2 * D], hn = gh[ghb + 2 * D];
    float r = 1.0f / (1.0f + __expf(-(ir + hr)));
    float z = 1.0f / (1.0f + __expf(-(iz + hz)));
    float nn = tanhf(in_ + r * hn);
    float hv = h[idx];
    float val = (1.0f - z) * nn + z * hv;
    if (mode == 1) {
        float qm = qmask[n];
        val = hv * (1.0f - qm) + val * qm;
    }
    out[idx] = val;
}

// =====================================================================
// launch
// =====================================================================
extern "C" void kernel_launch(void* const* d_in, const int* in_sizes, int n_in,
                              void* d_out, int out_size)
{
    const float* U       = (const float*)d_in[0];
    const float* qmask   = (const float*)d_in[1];
    const float* g_hist  = (const float*)d_in[2];
    const float* q0      = (const float*)d_in[3];
    const float* q_hist  = (const float*)d_in[4];
    const float* e0      = (const float*)d_in[5];
    const float* w_ih_g  = (const float*)d_in[6];
    const float* w_hh_g  = (const float*)d_in[7];
    const float* b_ih_g  = (const float*)d_in[8];
    const float* b_hh_g  = (const float*)d_in[9];
    const float* w_ih_p  = (const float*)d_in[10];
    const float* w_hh_p  = (const float*)d_in[11];
    const float* b_ih_p  = (const float*)d_in[12];
    const float* b_hh_p  = (const float*)d_in[13];
    const float* w_ih_e  = (const float*)d_in[14];
    const float* w_hh_e  = (const float*)d_in[15];
    const float* b_ih_e  = (const float*)d_in[16];
    const float* b_hh_e  = (const float*)d_in[17];
    const float* w_att   = (const float*)d_in[18];
    const float* w_trans = (const float*)d_in[19];
    float* out = (float*)d_out;

    static int smem_set = 0;
    if (!smem_set) {
        cudaFuncSetAttribute(fused_all, cudaFuncAttributeMaxDynamicSharedMemorySize, DYN_SMEM_BYTES);
        smem_set = 1;
    }

    float *gi_p, *gh_p, *ghe_p, *ghp_p, *xt_p, *gih_p;
    __nv_bfloat16* bf;
    cudaGetSymbolAddress((void**)&gi_p,   d_gi_buf);
    cudaGetSymbolAddress((void**)&gh_p,   d_gh_buf);
    cudaGetSymbolAddress((void**)&ghe_p,  d_ghe_buf);
    cudaGetSymbolAddress((void**)&ghp_p,  d_ghp_buf);
    cudaGetSymbolAddress((void**)&xt_p,   d_xt_buf);
    cudaGetSymbolAddress((void**)&gih_p,  d_gih_buf);
    cudaGetSymbolAddress((void**)&bf,     d_bf);

    const float* g_last = g_hist + (size_t)(Tn - 1) * Bn * D_G;

    // ---- L0: single conv launch (weights + activations + gathers) ----
    {
        CBatch cb; cb.nd = 13;
        int s = 0;
        auto add = [&](int i, const float* in, unsigned long long off,
                       int Kin, int Kout, int colofs, int total, int mode) {
            cb.d[i] = { in, bf + off, Kin, Kout, colofs, total, s, mode };
            s += (total + 2047) / 2048;
        };
        add(0,  w_ih_g,  OFF_WIHG,  1536, 1536, 0, 1536 * 1536, 1);
        add(1,  w_hh_g,  OFF_WHHG,  512,  512,  0, 1536 * 512,  1);
        add(2,  w_ih_p,  OFF_WIHP,  1536, 1536, 0, 1536 * 1536, 1);
        add(3,  w_hh_p,  OFF_WHHP,  512,  512,  0, 1536 * 512,  1);
        add(4,  w_ih_e,  OFF_WIHE,  512,  512,  0, 1536 * 512,  1);
        add(5,  w_hh_e,  OFF_WHHE,  512,  512,  0, 1536 * 512,  1);
        add(6,  w_trans, OFF_WTR,   512,  512,  0, 512 * 512,   1);
        add(7,  nullptr, OFF_XCG,   1536, 1536, 0, 512 * 1536,  2);   // [U|q0_sel] gather
        add(8,  g_last,  OFF_GLAST, 512,  512,  0, 512 * 512,   0);
        add(9,  q0,      OFF_Q0,    512,  512,  0, 1024 * 512,  0);
        add(10, nullptr, OFF_E0SW,  512,  512,  0, 1024 * 512,  3);   // e0 party-swap gather
        add(11, e0,      OFF_E0,    512,  512,  0, 1024 * 512,  0);
        add(12, U,       OFF_XCP,   1024, 1536, 0, 512 * 1024,  0);   // XCP U-columns
        conv_batch<<<s, 256>>>(cb, U, qmask, q0, e0);
    }

    // ---- L1: fused {gi_g, gh_g, gh_p, xt, gh_e} + attn_g (ordered) ----
    {
        TBatch tb; tb.nd = 5;
        int s = 0;
        tb.d[0] = { bf + OFF_XCG,   bf + OFF_WIHG, b_ih_g, gi_p,  4608, 3 * D_G, 12, s }; s += 48;
        tb.d[1] = { bf + OFF_GLAST, bf + OFF_WHHG, b_hh_g, gh_p,  1536, 3 * D_G, 12, s }; s += 48;
        tb.d[2] = { bf + OFF_Q0,    bf + OFF_WHHP, b_hh_p, ghp_p, 1536, 3 * D_P, 12, s }; s += 96;
        tb.d[3] = { bf + OFF_E0SW,  bf + OFF_WTR,  nullptr, xt_p, 1536, D_P,      4, s }; s += 32;
        tb.d[4] = { bf + OFF_E0,    bf + OFF_WHHE, b_hh_e, ghe_p, 1536, 3 * D_E, 12, s }; s += 96;
        int total = s + Bn;
        fused_all<<<total, 256, DYN_SMEM_BYTES>>>(tb, s, Bn, g_hist, w_att,
                                                  out + C_OFF, out + A_OFF, bf + OFF_XCP,
                                                  q_hist, xt_p, bf + OFF_QC);
    }

    // ---- L2: fused {gi_p} + attn_q (ordered) ----
    {
        TBatch tb; tb.nd = 1;
        tb.d[0] = { bf + OFF_XCP, bf + OFF_WIHP, b_ih_p, gih_p, 4608, 3 * D_P, 12, 0 };
        int s = 48;
        int total = s + Bn * PARTY;
        fused_all<<<total, 256, DYN_SMEM_BYTES>>>(tb, s, 0, g_hist, w_att,
                                                  nullptr, nullptr, nullptr,
                                                  q_hist, xt_p, bf + OFF_QC);
    }

    // ---- L3: epilogues g, p (plain kernels) ----
    gru_epi<<<(Bn * D_G + 255) / 256, 256>>>(gi_p, gh_p, g_last, out + G_OFF, Bn, D_G, 0, nullptr);
    gru_epi<<<(Bn * PARTY * D_P + 255) / 256, 256>>>(gih_p, ghp_p, q0, out + Q_OFF,
                                                     Bn * PARTY, D_P, 1, qmask);

    // ---- L4: gi_e (needs QC) ----
    {
        TBatch tb; tb.nd = 1;
        tb.d[0] = { bf + OFF_QC, bf + OFF_WIHE, b_ih_e, gi_p, 1536, 3 * D_E, 12, 0 };
        fused_all<<<96, 256, DYN_SMEM_BYTES>>>(tb, 96, 0, g_hist, w_att,
                                               nullptr, nullptr, nullptr,
                                               q_hist, xt_p, bf + OFF_QC);
    }

    // ---- L5: epilogue e ----
    gru_epi<<<(Bn * PARTY * D_E + 255) / 256, 256>>>(gi_p, ghe_p, e0, out + E_OFF,
                                                     Bn * PARTY, D_E, 0, nullptr);
}

// round 15
// speedup vs baseline: 1.4305x; 1.0559x over previous
#include <cuda_runtime.h>
#include <cuda_bf16.h>
#include <math.h>
#include <stdint.h>

#define Bn 512
#define Tn 200
#define PARTY 2
#define D_M 1024
#define D_G 512
#define D_P 512
#define D_E 512

// Output layout (flattened tuple): g_, q_, e_, c_, alpha_out
#define G_OFF 0
#define Q_OFF (Bn * D_G)
#define E_OFF (Q_OFF + Bn * PARTY * D_P)
#define C_OFF (E_OFF + Bn * PARTY * D_E)
#define A_OFF (C_OFF + Bn * D_G)

// ---------------- fp32 scratch ----------------
__device__ float d_xcg_buf[Bn * (D_M + D_P)];
__device__ float d_gi_buf[(Bn * PARTY) * 3 * D_G];    // gi_g ; later gi_e half 1
__device__ float d_gh_buf[Bn * 3 * D_G];              // gh_g
__device__ float d_ghe_buf[(Bn * PARTY) * 3 * D_E];   // gh_e
__device__ float d_ghp_buf[(Bn * PARTY) * 3 * D_P];   // gh_p ; later gi_e half 2
__device__ float d_xt_buf[Bn * PARTY * D_P];
__device__ float d_e0sw_buf[Bn * PARTY * D_E];
__device__ float d_gih_buf[Bn * 3 * D_P];             // gi_p dedup

// ---------------- bf16 split scratch (hi/lo concat, K tripled) ----------------
#define OFF_WIHG  0ull                       // 1536 x 4608
#define OFF_WHHG  (OFF_WIHG  + 7077888ull)   // 1536 x 1536
#define OFF_WIHP  (OFF_WHHG  + 2359296ull)   // 1536 x 4608
#define OFF_WHHP  (OFF_WIHP  + 7077888ull)   // 1536 x 1536
#define OFF_WIHE  (OFF_WHHP  + 2359296ull)   // 1536 x 1536
#define OFF_WHHE  (OFF_WIHE  + 2359296ull)   // 1536 x 1536
#define OFF_WTR   (OFF_WHHE  + 2359296ull)   // 512 x 1536
#define OFF_XCG   (OFF_WTR   + 786432ull)    // 512 x 4608
#define OFF_GLAST (OFF_XCG   + 2359296ull)   // 512 x 1536
#define OFF_Q0    (OFF_GLAST + 786432ull)    // 1024 x 1536
#define OFF_E0SW  (OFF_Q0    + 1572864ull)   // 1024 x 1536
#define OFF_E0    (OFF_E0SW  + 1572864ull)   // 1024 x 1536
#define OFF_XCP   (OFF_E0    + 1572864ull)   // 512 x 4608 (U-cols by conv; c_-cols by attn_g)
#define OFF_QC    (OFF_XCP   + 2359296ull)   // 1024 x 1536 (by attn_q)
#define BF_TOTAL  (OFF_QC    + 1572864ull)
__device__ __align__(16) __nv_bfloat16 d_bf[BF_TOTAL];

// =====================================================================
// helpers
// =====================================================================
__device__ __forceinline__ uint32_t smem_u32(const void* p) {
    uint32_t r;
    asm("{ .reg .u64 t; cvta.to.shared.u64 t, %1; cvt.u32.u64 %0, t; }" : "=r"(r) : "l"(p));
    return r;
}
__device__ __forceinline__ void cp_async16(uint32_t dst, const void* src) {
    asm volatile("cp.async.cg.shared.global [%0], [%1], 16;" :: "r"(dst), "l"(src) : "memory");
}
__device__ __forceinline__ void cp_commit() {
    asm volatile("cp.async.commit_group;" ::: "memory");
}
template<int N>
__device__ __forceinline__ void cp_wait() {
    asm volatile("cp.async.wait_group %0;" :: "n"(N) : "memory");
}
__device__ __forceinline__ void ldmatrix_x4(uint32_t& r0, uint32_t& r1, uint32_t& r2, uint32_t& r3,
                                            uint32_t addr) {
    asm volatile("ldmatrix.sync.aligned.m8n8.x4.shared.b16 {%0,%1,%2,%3}, [%4];"
                 : "=r"(r0), "=r"(r1), "=r"(r2), "=r"(r3) : "r"(addr));
}
__device__ __forceinline__ void mma_bf16(float* d, const uint32_t* a, const uint32_t* b) {
    asm volatile("mma.sync.aligned.m16n8k16.row.col.f32.bf16.bf16.f32 "
                 "{%0,%1,%2,%3}, {%4,%5,%6,%7}, {%8,%9}, {%0,%1,%2,%3};"
                 : "+f"(d[0]), "+f"(d[1]), "+f"(d[2]), "+f"(d[3])
                 : "r"(a[0]), "r"(a[1]), "r"(a[2]), "r"(a[3]), "r"(b[0]), "r"(b[1]));
}
__device__ __forceinline__ void lds128(float* v, uint32_t addr) {
    asm volatile("ld.shared.v4.f32 {%0,%1,%2,%3}, [%4];"
                 : "=f"(v[0]), "=f"(v[1]), "=f"(v[2]), "=f"(v[3]) : "r"(addr));
}
__device__ __forceinline__ void split3(float x, __nv_bfloat16* o, int stride) {
    __nv_bfloat16 hi = __float2bfloat16(x);
    __nv_bfloat16 lo = __float2bfloat16(x - __bfloat162float(hi));
    o[0] = hi; o[stride] = lo; o[2 * stride] = hi;
}

// =====================================================================
// Attention body (R10-proven): per-warp online softmax, 2-deep BLOCK
// cp.async staging. Smem: [tile0 16KB][tile1 16KB][AttnSmem]
// MODE 0: attn_q (write QC bf16). MODE 1: attn_g (c_, alpha, XCP bf16).
// =====================================================================
struct AttnSmem {
    float m[8]; float s[8]; float w8[8];
    float Mg, Sg;
    float sc[Tn];
    float acc[8][512];
};
#define ATTN_TILE_BYTES 16384
#define ATTN_SM_OFF (2 * ATTN_TILE_BYTES)
#define DYN_SMEM_BYTES 65536

template<int MODE>
__device__ __forceinline__ void attn_body(
    char* smem_raw,
    const float* __restrict__ hist, size_t tstride, size_t row_off,
    const float* __restrict__ wvec,
    float* __restrict__ c_out,
    float* __restrict__ alpha_out,
    __nv_bfloat16* __restrict__ bf_out,
    int bf_stride)
{
    uint32_t sb = smem_u32(smem_raw);
    AttnSmem* sm = reinterpret_cast<AttnSmem*>(smem_raw + ATTN_SM_OFF);
    int tid = threadIdx.x;
    int lane = tid & 31;
    int w = tid >> 5;

    const float* src = hist + row_off;

    int trow_[4], c16_[4];
    #pragma unroll
    for (int i = 0; i < 4; i++) {
        int u = tid + 256 * i;
        trow_[i] = u >> 7;
        c16_[i] = u & 127;
    }

    float q[16];
    #pragma unroll
    for (int j = 0; j < 4; j++) {
        float4 t4 = *(const float4*)(wvec + lane * 4 + j * 128);
        q[j*4+0] = t4.x; q[j*4+1] = t4.y; q[j*4+2] = t4.z; q[j*4+3] = t4.w;
    }

    float m = -INFINITY, s = 0.0f;
    float acc[16];
    #pragma unroll
    for (int k = 0; k < 16; k++) acc[k] = 0.0f;

    // prologue: chunks 0, 1
    #pragma unroll
    for (int c = 0; c < 2; c++) {
        uint32_t dst = sb + (uint32_t)c * ATTN_TILE_BYTES;
        #pragma unroll
        for (int i = 0; i < 4; i++) {
            cp_async16(dst + (uint32_t)(trow_[i] * 2048 + c16_[i] * 16),
                       src + (size_t)(c * 8 + trow_[i]) * tstride + c16_[i] * 4);
        }
        cp_commit();
    }

    for (int i = 0; i < 25; i++) {
        if (i == 24) cp_wait<0>(); else cp_wait<1>();
        __syncthreads();

        uint32_t vbase = sb + (uint32_t)(i & 1) * ATTN_TILE_BYTES + (uint32_t)(w * 2048 + lane * 16);
        float v[16];
        #pragma unroll
        for (int j = 0; j < 4; j++) lds128(v + j * 4, vbase + j * 512);

        int t = i * 8 + w;
        float dot = 0.0f;
        #pragma unroll
        for (int k = 0; k < 16; k++) dot = fmaf(v[k], q[k], dot);
        #pragma unroll
        for (int o = 16; o > 0; o >>= 1) dot += __shfl_xor_sync(0xffffffffu, dot, o);

        if (MODE == 1 && lane == 0) sm->sc[t] = dot;

        float nm = fmaxf(m, dot);
        float rs = __expf(m - nm);
        float cf = __expf(dot - nm);
        #pragma unroll
        for (int k = 0; k < 16; k++) acc[k] = fmaf(acc[k], rs, cf * v[k]);
        s = fmaf(s, rs, cf);
        m = nm;

        __syncthreads();
        if (i + 2 < 25) {
            uint32_t dst = sb + (uint32_t)(i & 1) * ATTN_TILE_BYTES;
            #pragma unroll
            for (int j = 0; j < 4; j++) {
                cp_async16(dst + (uint32_t)(trow_[j] * 2048 + c16_[j] * 16),
                           src + (size_t)((i + 2) * 8 + trow_[j]) * tstride + c16_[j] * 4);
            }
            cp_commit();
        }
    }

    if (lane == 0) { sm->m[w] = m; sm->s[w] = s; }
    #pragma unroll
    for (int j = 0; j < 4; j++)
        #pragma unroll
        for (int u = 0; u < 4; u++)
            sm->acc[w][lane * 4 + j * 128 + u] = acc[j*4+u];
    __syncthreads();

    if (tid == 0) {
        float M = -INFINITY;
        #pragma unroll
        for (int k = 0; k < 8; k++) M = fmaxf(M, sm->m[k]);
        float S = 0.0f;
        #pragma unroll
        for (int k = 0; k < 8; k++) S += sm->s[k] * __expf(sm->m[k] - M);
        float invS = 1.0f / S;
        #pragma unroll
        for (int k = 0; k < 8; k++) sm->w8[k] = __expf(sm->m[k] - M) * invS;
        sm->Mg = M; sm->Sg = S;
    }
    __syncthreads();

    int c = tid * 2;
    float o0 = 0.0f, o1 = 0.0f;
    #pragma unroll
    for (int k = 0; k < 8; k++) {
        float wk = sm->w8[k];
        o0 = fmaf(sm->acc[k][c], wk, o0);
        o1 = fmaf(sm->acc[k][c + 1], wk, o1);
    }
    if (MODE == 1) {
        *(float2*)(c_out + c) = make_float2(o0, o1);
        split3(o0, bf_out + c,     bf_stride);
        split3(o1, bf_out + c + 1, bf_stride);
        if (tid < Tn) {
            float inv = 1.0f / sm->Sg;
            alpha_out[tid] = __expf(sm->sc[tid] - sm->Mg) * inv;
        }
    } else {
        split3(o0, bf_out + c,     bf_stride);
        split3(o1, bf_out + c + 1, bf_stride);
    }
}

// =====================================================================
// bf16 mma.sync GEMM body (R7-proven) — now with lda separate from K3
// so descriptors can K-split a matrix (stride != loop bound).
// =====================================================================
#define MAXT 5
struct TDesc {
    const __nv_bfloat16* A; const __nv_bfloat16* W;
    const float* bias; float* C;
    int lda; int K3; int M; int gridX; int start;
};
struct TBatch { TDesc d[MAXT]; int nd; };

__device__ __forceinline__ void mma_gemm_body(const TBatch& tb, char* smem_raw, int bid)
{
    int tid = threadIdx.x;
    int wid = tid >> 5;
    int lane = tid & 31;

    int di = 0;
    #pragma unroll
    for (int k = 1; k < MAXT; k++)
        if (k < tb.nd && bid >= tb.d[k].start) di = k;
    const TDesc dd = tb.d[di];
    int local = bid - dd.start;
    int m0 = (local % dd.gridX) * 128;
    int n0 = (local / dd.gridX) * 128;
    const int K3 = dd.K3;
    const int lda = dd.lda;
    const int nc = K3 >> 6;

    uint32_t sb = smem_u32(smem_raw);

    int lrow[4], lc16[4]; uint32_t swoff[4];
    #pragma unroll
    for (int i = 0; i < 4; i++) {
        int u = tid + 256 * i;
        int r = u >> 3, c16 = u & 7;
        lrow[i] = r; lc16[i] = c16;
        swoff[i] = (uint32_t)(r * 128 + 16 * (c16 ^ (r & 7)));
    }
    const __nv_bfloat16* Ab = dd.A + (size_t)n0 * lda;
    const __nv_bfloat16* Wb = dd.W + (size_t)m0 * lda;

    int xr = lane & 7;
    int lA_row = (lane & 7) + ((lane >> 3) & 1) * 8;
    int lA_kh = lane >> 4;
    int lB_row = (lane & 7) + (lane >> 4) * 8;
    int lB_kh = (lane >> 3) & 1;
    int wr = wid & 1;
    int wc = wid >> 1;
    uint32_t rbA[4], rbB[2];
    #pragma unroll
    for (int mt = 0; mt < 4; mt++) rbA[mt] = (uint32_t)((wr * 64 + mt * 16 + lA_row) * 128);
    #pragma unroll
    for (int p = 0; p < 2; p++) rbB[p] = (uint32_t)((wc * 32 + p * 16 + lB_row) * 128);

    float acc[4][4][4];
    #pragma unroll
    for (int mt = 0; mt < 4; mt++)
        #pragma unroll
        for (int nt = 0; nt < 4; nt++)
            #pragma unroll
            for (int r = 0; r < 4; r++) acc[mt][nt][r] = 0.0f;

    {
        uint32_t ba = sb, bb = sb + 16384u;
        #pragma unroll
        for (int i = 0; i < 4; i++) {
            cp_async16(ba + swoff[i], Ab + (size_t)lrow[i] * lda + lc16[i] * 8);
            cp_async16(bb + swoff[i], Wb + (size_t)lrow[i] * lda + lc16[i] * 8);
        }
        cp_commit();
    }

    for (int c = 0; c < nc; c++) {
        if (c + 1 < nc) {
            uint32_t ba = sb + (uint32_t)((c + 1) & 1) * 32768u;
            uint32_t bb = ba + 16384u;
            int koff = (c + 1) * 64;
            #pragma unroll
            for (int i = 0; i < 4; i++) {
                cp_async16(ba + swoff[i], Ab + (size_t)lrow[i] * lda + koff + lc16[i] * 8);
                cp_async16(bb + swoff[i], Wb + (size_t)lrow[i] * lda + koff + lc16[i] * 8);
            }
            cp_commit();
            cp_wait<1>();
        } else {
            cp_wait<0>();
        }
        __syncthreads();

        uint32_t ba = sb + (uint32_t)(c & 1) * 32768u;
        uint32_t bb = ba + 16384u;
        #pragma unroll
        for (int s = 0; s < 4; s++) {
            uint32_t a[4][4];
            #pragma unroll
            for (int mt = 0; mt < 4; mt++) {
                uint32_t addr = ba + rbA[mt] + 16u * (uint32_t)(((s << 1) + lA_kh) ^ xr);
                ldmatrix_x4(a[mt][0], a[mt][1], a[mt][2], a[mt][3], addr);
            }
            uint32_t bfr[4][2];
            #pragma unroll
            for (int p = 0; p < 2; p++) {
                uint32_t addr = bb + rbB[p] + 16u * (uint32_t)(((s << 1) + lB_kh) ^ xr);
                ldmatrix_x4(bfr[2*p][0], bfr[2*p][1], bfr[2*p+1][0], bfr[2*p+1][1], addr);
            }
            #pragma unroll
            for (int mt = 0; mt < 4; mt++)
                #pragma unroll
                for (int nt = 0; nt < 4; nt++)
                    mma_bf16(acc[mt][nt], a[mt], bfr[nt]);
        }
        __syncthreads();
    }

    int g = lane >> 2;
    int t2 = (lane & 3) * 2;
    #pragma unroll
    for (int mt = 0; mt < 4; mt++) {
        int row0 = n0 + wr * 64 + mt * 16 + g;
        #pragma unroll
        for (int nt = 0; nt < 4; nt++) {
            int col = m0 + wc * 32 + nt * 8 + t2;
            float b0 = 0.0f, b1 = 0.0f;
            if (dd.bias) { b0 = dd.bias[col]; b1 = dd.bias[col + 1]; }
            float2 v0 = make_float2(acc[mt][nt][0] + b0, acc[mt][nt][1] + b1);
            float2 v1 = make_float2(acc[mt][nt][2] + b0, acc[mt][nt][3] + b1);
            *(float2*)(dd.C + (size_t)row0 * dd.M + col) = v0;
            *(float2*)(dd.C + (size_t)(row0 + 8) * dd.M + col) = v1;
        }
    }
}

// =====================================================================
// Fused launch, ORDERED (gemm-first):
// [0,ng) gemm | [ng, ng+nag) attn_g | rest attn_q
// =====================================================================
__global__ __launch_bounds__(256, 2) void fused_all(
    TBatch tb, int n_gemm, int n_attn_g,
    const float* __restrict__ g_hist, const float* __restrict__ w_att,
    float* __restrict__ c_out, float* __restrict__ alpha_base,
    __nv_bfloat16* __restrict__ xcp_bf,
    const float* __restrict__ q_hist, const float* __restrict__ xt,
    __nv_bfloat16* __restrict__ qc_bf)
{
    extern __shared__ __align__(128) char smem_raw[];
    int bid = blockIdx.x;
    if (bid < n_gemm) {
        mma_gemm_body(tb, smem_raw, bid);
    } else if (bid < n_gemm + n_attn_g) {
        int b = bid - n_gemm;
        attn_body<1>(smem_raw, g_hist, (size_t)Bn * D_G, (size_t)b * D_G,
                     w_att,
                     c_out + (size_t)b * D_G,
                     alpha_base + (size_t)b * Tn,
                     xcp_bf + (size_t)b * 4608 + 1024, 1536);
    } else {
        int n = bid - n_gemm - n_attn_g;
        attn_body<0>(smem_raw, q_hist, (size_t)Bn * PARTY * D_P, (size_t)n * D_P,
                     xt + (size_t)n * D_P,
                     nullptr, nullptr,
                     qc_bf + (size_t)n * 1536, 512);
    }
}

// =====================================================================
// conversions (R10's plain batched form)
// mode 0: activation [hi|lo|hi]  mode 1: weight [hi|hi|lo]
// =====================================================================
#define MAXC 13
struct CDesc { const float* in; __nv_bfloat16* out; int Kin; int Kout; int colofs; int total; int start; int mode; };
struct CBatch { CDesc d[MAXC]; int nd; };

__global__ __launch_bounds__(256) void conv_batch(CBatch cb)
{
    int bid = blockIdx.x;
    int di = 0;
    #pragma unroll
    for (int k = 1; k < MAXC; k++)
        if (k < cb.nd && bid >= cb.d[k].start) di = k;
    const CDesc dd = cb.d[di];
    int base = (bid - dd.start) * 2048 + threadIdx.x;
    #pragma unroll
    for (int i = 0; i < 8; i++) {
        int idx = base + i * 256;
        if (idx >= dd.total) break;
        int r = idx / dd.Kin;
        int k = idx - r * dd.Kin;
        float x = dd.in[idx];
        __nv_bfloat16 hi = __float2bfloat16(x);
        __nv_bfloat16 lo = __float2bfloat16(x - __bfloat162float(hi));
        __nv_bfloat16* o = dd.out + (size_t)r * 3 * dd.Kout + dd.colofs + k;
        if (dd.mode == 1) { o[0] = hi; o[dd.Kout] = hi; o[2 * dd.Kout] = lo; }
        else              { o[0] = hi; o[dd.Kout] = lo; o[2 * dd.Kout] = hi; }
    }
}

// =====================================================================
// GRU epilogues (plain lightweight kernels)
// =====================================================================
__device__ __forceinline__ void gru_elem(
    const float* gi, const float* gi2, const float* gh,
    const float* h, float* out, int N, int D, int mode,
    const float* qmask, int idx)
{
    if (idx >= N * D) return;
    int n = idx / D;
    int j = idx - n * D;
    int gn = (mode == 1) ? (n >> 1) : n;
    size_t gib = (size_t)gn * 3 * D + j;
    size_t ghb = (size_t)n * 3 * D + j;
    float ir = gi[gib],          hr = gh[ghb];
    float iz = gi[gib + D],      hz = gh[ghb + D];
    float in_ = gi[gib + 2 * D], hn = gh[ghb + 2 * D];
    if (gi2) { ir += gi2[gib]; iz += gi2[gib + D]; in_ += gi2[gib + 2 * D]; }
    float r = 1.0f / (1.0f + __expf(-(ir + hr)));
    float z = 1.0f / (1.0f + __expf(-(iz + hz)));
    float nn = tanhf(in_ + r * hn);
    float hv = h[idx];
    float val = (1.0f - z) * nn + z * hv;
    if (mode == 1) {
        float qm = qmask[n];
        val = hv * (1.0f - qm) + val * qm;
    }
    out[idx] = val;
}

// merged g+p epilogue: blocks [0,1024) -> g, [1024, 3072) -> p
__global__ void gru_epi_gp(const float* __restrict__ gi_g, const float* __restrict__ gh_g,
                           const float* __restrict__ g_last, float* __restrict__ out_g,
                           const float* __restrict__ gi_ph, const float* __restrict__ gh_ph,
                           const float* __restrict__ q0, float* __restrict__ out_q,
                           const float* __restrict__ qmask)
{
    int blk = blockIdx.x;
    if (blk < 1024) {
        gru_elem(gi_g, nullptr, gh_g, g_last, out_g, Bn, D_G, 0, nullptr,
                 blk * 256 + threadIdx.x);
    } else {
        gru_elem(gi_ph, nullptr, gh_ph, q0, out_q, Bn * PARTY, D_P, 1, qmask,
                 (blk - 1024) * 256 + threadIdx.x);
    }
}

// e epilogue with K-split addend
__global__ void gru_epi_e(const float* __restrict__ gi, const float* __restrict__ gi2,
                          const float* __restrict__ gh, const float* __restrict__ e0,
                          float* __restrict__ out)
{
    gru_elem(gi, gi2, gh, e0, out, Bn * PARTY, D_E, 0, nullptr,
             blockIdx.x * 256 + threadIdx.x);
}

// ---------------- small builders (R10-proven) ----------------
__global__ void build_xcat_g(const float* __restrict__ U, const float* __restrict__ qmask,
                             const float* __restrict__ q0, float* __restrict__ xcat)
{
    int idx = blockIdx.x * blockDim.x + threadIdx.x;
    const int W = D_M + D_P;
    if (idx >= Bn * W) return;
    int b = idx / W;
    int c = idx - b * W;
    float v;
    if (c < D_M) {
        v = U[(size_t)b * D_M + c];
    } else {
        int qi = (qmask[b * 2 + 1] > qmask[b * 2 + 0]) ? 1 : 0;
        v = q0[(size_t)(b * 2 + qi) * D_P + (c - D_M)];
    }
    xcat[idx] = v;
}

__global__ void build_e0sw(const float* __restrict__ e0, float* __restrict__ e0sw)
{
    int idx = blockIdx.x * blockDim.x + threadIdx.x;
    if (idx >= Bn * PARTY * D_E) return;
    int n = idx / D_E;
    int j = idx - n * D_E;
    int b = n >> 1;
    int p = n & 1;
    e0sw[idx] = e0[(size_t)(b * 2 + (1 - p)) * D_E + j];
}

// =====================================================================
// launch
// =====================================================================
extern "C" void kernel_launch(void* const* d_in, const int* in_sizes, int n_in,
                              void* d_out, int out_size)
{
    const float* U       = (const float*)d_in[0];
    const float* qmask   = (const float*)d_in[1];
    const float* g_hist  = (const float*)d_in[2];
    const float* q0      = (const float*)d_in[3];
    const float* q_hist  = (const float*)d_in[4];
    const float* e0      = (const float*)d_in[5];
    const float* w_ih_g  = (const float*)d_in[6];
    const float* w_hh_g  = (const float*)d_in[7];
    const float* b_ih_g  = (const float*)d_in[8];
    const float* b_hh_g  = (const float*)d_in[9];
    const float* w_ih_p  = (const float*)d_in[10];
    const float* w_hh_p  = (const float*)d_in[11];
    const float* b_ih_p  = (const float*)d_in[12];
    const float* b_hh_p  = (const float*)d_in[13];
    const float* w_ih_e  = (const float*)d_in[14];
    const float* w_hh_e  = (const float*)d_in[15];
    const float* b_ih_e  = (const float*)d_in[16];
    const float* b_hh_e  = (const float*)d_in[17];
    const float* w_att   = (const float*)d_in[18];
    const float* w_trans = (const float*)d_in[19];
    float* out = (float*)d_out;

    static int smem_set = 0;
    if (!smem_set) {
        cudaFuncSetAttribute(fused_all, cudaFuncAttributeMaxDynamicSharedMemorySize, DYN_SMEM_BYTES);
        smem_set = 1;
    }

    float *xcg_p, *gi_p, *gh_p, *ghe_p, *ghp_p, *xt_p, *e0sw_p, *gih_p;
    __nv_bfloat16* bf;
    cudaGetSymbolAddress((void**)&xcg_p,  d_xcg_buf);
    cudaGetSymbolAddress((void**)&gi_p,   d_gi_buf);
    cudaGetSymbolAddress((void**)&gh_p,   d_gh_buf);
    cudaGetSymbolAddress((void**)&ghe_p,  d_ghe_buf);
    cudaGetSymbolAddress((void**)&ghp_p,  d_ghp_buf);
    cudaGetSymbolAddress((void**)&xt_p,   d_xt_buf);
    cudaGetSymbolAddress((void**)&e0sw_p, d_e0sw_buf);
    cudaGetSymbolAddress((void**)&gih_p,  d_gih_buf);
    cudaGetSymbolAddress((void**)&bf,     d_bf);

    const float* g_last = g_hist + (size_t)(Tn - 1) * Bn * D_G;

    // ---- L0: builders + all independent conversions ----
    build_xcat_g<<<(Bn * (D_M + D_P) + 255) / 256, 256>>>(U, qmask, q0, xcg_p);
    build_e0sw<<<(Bn * PARTY * D_E + 255) / 256, 256>>>(e0, e0sw_p);
    {
        CBatch cb; cb.nd = 13;
        int s = 0;
        auto add = [&](int i, const float* in, unsigned long long off,
                       int Kin, int Kout, int colofs, int total, int mode) {
            cb.d[i] = { in, bf + off, Kin, Kout, colofs, total, s, mode };
            s += (total + 2047) / 2048;
        };
        add(0,  w_ih_g,  OFF_WIHG,  1536, 1536, 0, 1536 * 1536, 1);
        add(1,  w_hh_g,  OFF_WHHG,  512,  512,  0, 1536 * 512,  1);
        add(2,  w_ih_p,  OFF_WIHP,  1536, 1536, 0, 1536 * 1536, 1);
        add(3,  w_hh_p,  OFF_WHHP,  512,  512,  0, 1536 * 512,  1);
        add(4,  w_ih_e,  OFF_WIHE,  512,  512,  0, 1536 * 512,  1);
        add(5,  w_hh_e,  OFF_WHHE,  512,  512,  0, 1536 * 512,  1);
        add(6,  w_trans, OFF_WTR,   512,  512,  0, 512 * 512,   1);
        add(7,  xcg_p,   OFF_XCG,   1536, 1536, 0, 512 * 1536,  0);
        add(8,  g_last,  OFF_GLAST, 512,  512,  0, 512 * 512,   0);
        add(9,  q0,      OFF_Q0,    512,  512,  0, 1024 * 512,  0);
        add(10, e0sw_p,  OFF_E0SW,  512,  512,  0, 1024 * 512,  0);
        add(11, e0,      OFF_E0,    512,  512,  0, 1024 * 512,  0);
        add(12, U,       OFF_XCP,   1024, 1536, 0, 512 * 1024,  0);   // XCP U-columns
        conv_batch<<<s, 256>>>(cb);
    }

    // ---- L1: fused {gi_g, gh_g, gh_p, xt, gh_e} + attn_g (ordered) ----
    {
        TBatch tb; tb.nd = 5;
        int s = 0;
        tb.d[0] = { bf + OFF_XCG,   bf + OFF_WIHG, b_ih_g, gi_p,  4608, 4608, 3 * D_G, 12, s }; s += 48;
        tb.d[1] = { bf + OFF_GLAST, bf + OFF_WHHG, b_hh_g, gh_p,  1536, 1536, 3 * D_G, 12, s }; s += 48;
        tb.d[2] = { bf + OFF_Q0,    bf + OFF_WHHP, b_hh_p, ghp_p, 1536, 1536, 3 * D_P, 12, s }; s += 96;
        tb.d[3] = { bf + OFF_E0SW,  bf + OFF_WTR,  nullptr, xt_p, 1536, 1536, D_P,      4, s }; s += 32;
        tb.d[4] = { bf + OFF_E0,    bf + OFF_WHHE, b_hh_e, ghe_p, 1536, 1536, 3 * D_E, 12, s }; s += 96;
        int total = s + Bn;
        fused_all<<<total, 256, DYN_SMEM_BYTES>>>(tb, s, Bn, g_hist, w_att,
                                                  out + C_OFF, out + A_OFF, bf + OFF_XCP,
                                                  q_hist, xt_p, bf + OFF_QC);
    }

    // ---- L2: fused {gi_p} + attn_q (ordered) ----
    {
        TBatch tb; tb.nd = 1;
        tb.d[0] = { bf + OFF_XCP, bf + OFF_WIHP, b_ih_p, gih_p, 4608, 4608, 3 * D_P, 12, 0 };
        int s = 48;
        int total = s + Bn * PARTY;
        fused_all<<<total, 256, DYN_SMEM_BYTES>>>(tb, s, 0, g_hist, w_att,
                                                  nullptr, nullptr, nullptr,
                                                  q_hist, xt_p, bf + OFF_QC);
    }

    // ---- L3: merged epilogues g + p (single plain launch) ----
    gru_epi_gp<<<3072, 256>>>(gi_p, gh_p, g_last, out + G_OFF,
                              gih_p, ghp_p, q0, out + Q_OFF, qmask);

    // ---- L4: gi_e, K-split x2 (halves into gi_p and ghp_p buffers) ----
    {
        TBatch tb; tb.nd = 2;
        tb.d[0] = { bf + OFF_QC,       bf + OFF_WIHE,       b_ih_e,  gi_p,  1536, 768, 3 * D_E, 12, 0 };
        tb.d[1] = { bf + OFF_QC + 768, bf + OFF_WIHE + 768, nullptr, ghp_p, 1536, 768, 3 * D_E, 12, 96 };
        fused_all<<<192, 256, DYN_SMEM_BYTES>>>(tb, 192, 0, g_hist, w_att,
                                                nullptr, nullptr, nullptr,
                                                q_hist, xt_p, bf + OFF_QC);
    }

    // ---- L5: epilogue e (sums the two K-halves) ----
    gru_epi_e<<<(Bn * PARTY * D_E + 255) / 256, 256>>>(gi_p, ghp_p, ghe_p, e0, out + E_OFF);
}